// round 9
// baseline (speedup 1.0000x reference)
#include <cuda_runtime.h>
#include <cuda_bf16.h>
#include <math.h>

// ---------------------------------------------------------------------------
//   x: (8,16,3,84,84)  B=8 T=16  -> BT=128 frames
//   enc: 3->64 (pool), 64->128 (pool), 128->256    @84/42/21
//   ConvLSTM: depthwise 3x3 g=512, pointwise 512->1024, gates
//   dec: up2 conv 256->128 @42, up2 conv 128->64 @84, 1x1 64->1
//   Halo-padded buffers; smem fills are linear float4 copies.
//   Big kernels use dynamic smem (>48KB) to halve K-chunk count.
// ---------------------------------------------------------------------------

#define BT   128
#define BB   8
#define TT   16
#define HD   256
#define NP2  441
#define NP0  7056
#define OUTN 903168

#define E1S  1936   // 44*44 padded channel (42x42 interior)
#define E2S  544    // 23*23=529 padded to 544 (21x21 interior)
#define GWS  448    // 441 padded to 448
#define D1S  1936   // 44*44 padded channel (42x42 interior)

__device__ float g_e1p [(size_t)BT * 64  * E1S];
__device__ float g_e2p [(size_t)BT * 128 * E2S];
__device__ float g_feat[(size_t)BT * 256 * NP2];
__device__ float g_gdwf[(size_t)BT * 256 * GWS];
__device__ float g_gdwh[(size_t)BB * 256 * GWS];
__device__ float g_hsp [(size_t)BT * 256 * E2S];
__device__ float g_d1p [(size_t)BT * 128 * D1S];
__device__ float g_d2  [(size_t)BT * 64  * NP0];
__device__ float g_h   [BB * HD * NP2];
__device__ float g_c   [BB * HD * NP2];

__device__ __forceinline__ float sigm(float x) { return 1.0f / (1.0f + expf(-x)); }

// zero only the halo border + stride tail of padded channels.
// grid = #channels, block = 64.
__global__ void k_border(float* buf, int S, int W2, int H2)
{
    float* ch = buf + (size_t)blockIdx.x * S;
    const int nside = H2 - 2;
    const int nb = 2 * W2 + 2 * nside + (S - W2 * H2);
    for (int i = threadIdx.x; i < nb; i += 64) {
        int pos;
        if (i < W2)                       pos = i;
        else if (i < 2 * W2)              pos = (H2 - 1) * W2 + (i - W2);
        else if (i < 2 * W2 + nside)      pos = (i - 2 * W2 + 1) * W2;
        else if (i < 2 * W2 + 2 * nside)  pos = (i - 2 * W2 - nside + 1) * W2 + (W2 - 1);
        else                              pos = W2 * H2 + (i - 2 * W2 - 2 * nside);
        ch[pos] = 0.0f;
    }
}

__global__ void k_zero_hc()
{
    int i = blockIdx.x * blockDim.x + threadIdx.x;
    if (i < BB * HD * NP2) { g_h[i] = 0.0f; g_c[i] = 0.0f; }
}

// ---------------------------------------------------------------------------
// enc1: conv3x3 3->64 + bias + relu + maxpool2.  84x84 -> 42x42 into e1p pad.
// ---------------------------------------------------------------------------
__global__ void __launch_bounds__(448) k_enc1(
    const float* __restrict__ x, const float* __restrict__ w,
    const float* __restrict__ bias)
{
    __shared__ float s_in[3 * 44 * 44];
    __shared__ __align__(16) float s_w[3 * 9 * 64];

    const int n   = blockIdx.z;
    const int bx  = blockIdx.x;
    const int py0 = (bx >> 1) * 21;
    const int px0 = (bx & 1) * 21;
    const int oy0 = py0 * 2;
    const int ox0 = px0 * 2;
    const int tid = threadIdx.x;

    const float* xn = x + (size_t)n * 3 * NP0;

    for (int idx = tid; idx < 3 * 44 * 44; idx += 448) {
        int ci = idx / 1936, rem = idx % 1936;
        int r = rem / 44, c = rem % 44;
        int gy = oy0 - 1 + r, gx = ox0 - 1 + c;
        float v = 0.0f;
        if (gy >= 0 && gy < 84 && gx >= 0 && gx < 84)
            v = xn[(size_t)ci * NP0 + gy * 84 + gx];
        s_in[idx] = v;
    }
    for (int idx = tid; idx < 3 * 9 * 64; idx += 448) {
        int ci = idx / (9 * 64); int k = (idx % (9 * 64)) / 64; int co = idx % 64;
        s_w[idx] = w[((size_t)co * 3 + ci) * 9 + k];
    }
    __syncthreads();
    if (tid >= 441) return;

    const int ty = tid / 21, tx = tid % 21;
    const int by = 2 * ty, bxp = 2 * tx;

    for (int cg = 0; cg < 8; cg++) {
        float acc[8][4];
        #pragma unroll
        for (int j = 0; j < 8; j++) { acc[j][0]=acc[j][1]=acc[j][2]=acc[j][3]=0.f; }
        #pragma unroll
        for (int ci = 0; ci < 3; ci++) {
            const float* si = &s_in[ci * 1936];
            #pragma unroll
            for (int k = 0; k < 9; k++) {
                int dy = k / 3, dx = k % 3;
                const float* p0 = si + (by + dy) * 44 + (bxp + dx);
                float v00 = p0[0], v01 = p0[1], v10 = p0[44], v11 = p0[45];
                float4 wA = *(const float4*)&s_w[(ci * 9 + k) * 64 + cg * 8];
                float4 wB = *(const float4*)&s_w[(ci * 9 + k) * 64 + cg * 8 + 4];
                float wv[8] = {wA.x, wA.y, wA.z, wA.w, wB.x, wB.y, wB.z, wB.w};
                #pragma unroll
                for (int j = 0; j < 8; j++) {
                    acc[j][0] += v00 * wv[j];
                    acc[j][1] += v01 * wv[j];
                    acc[j][2] += v10 * wv[j];
                    acc[j][3] += v11 * wv[j];
                }
            }
        }
        #pragma unroll
        for (int j = 0; j < 8; j++) {
            int co = cg * 8 + j;
            float m = fmaxf(fmaxf(acc[j][0], acc[j][1]), fmaxf(acc[j][2], acc[j][3]));
            m = fmaxf(m + bias[co], 0.0f);
            g_e1p[((size_t)n * 64 + co) * E1S + (py0 + ty + 1) * 44 + (px0 + tx + 1)] = m;
        }
    }
}

// ---------------------------------------------------------------------------
// enc2: conv3x3 64->128 + bias + relu + maxpool2 @42 -> 21 into e2p pad.
// CC=8, dynamic smem (64.3KB), 8 chunks.
// ---------------------------------------------------------------------------
#define ENC2_CC 8
__global__ void __launch_bounds__(448) k_enc2(
    const float* __restrict__ w, const float* __restrict__ bias)
{
    extern __shared__ float smem[];
    float* s_in = smem;                       // ENC2_CC * E1S
    float* s_w  = smem + ENC2_CC * E1S;       // ENC2_CC * 72

    const int n   = blockIdx.z;
    const int coB = blockIdx.y * 8;
    const int tid = threadIdx.x;
    const int ty = tid / 21, tx = tid % 21;
    const int by = 2 * ty, bxp = 2 * tx;

    float acc[8][4];
    #pragma unroll
    for (int j = 0; j < 8; j++) { acc[j][0]=acc[j][1]=acc[j][2]=acc[j][3]=0.f; }

    for (int cc = 0; cc < 64; cc += ENC2_CC) {
        const float4* src4 = (const float4*)&g_e1p[((size_t)n * 64 + cc) * E1S];
        float4* dst4 = (float4*)s_in;
        #pragma unroll 1
        for (int idx = tid; idx < ENC2_CC * (E1S / 4); idx += 448) dst4[idx] = src4[idx];
        for (int idx = tid; idx < ENC2_CC * 72; idx += 448) {
            int ci = idx / 72; int k = (idx % 72) / 8; int co = idx % 8;
            s_w[idx] = w[((size_t)(coB + co) * 64 + (cc + ci)) * 9 + k];
        }
        __syncthreads();
        if (tid < 441) {
            #pragma unroll
            for (int ci = 0; ci < ENC2_CC; ci++) {
                const float* si = &s_in[ci * E1S];
                #pragma unroll
                for (int k = 0; k < 9; k++) {
                    int dy = k / 3, dx = k % 3;
                    const float* p0 = si + (by + dy) * 44 + (bxp + dx);
                    float v00 = p0[0], v01 = p0[1], v10 = p0[44], v11 = p0[45];
                    float4 wA = *(const float4*)&s_w[(ci * 9 + k) * 8];
                    float4 wB = *(const float4*)&s_w[(ci * 9 + k) * 8 + 4];
                    float wv[8] = {wA.x, wA.y, wA.z, wA.w, wB.x, wB.y, wB.z, wB.w};
                    #pragma unroll
                    for (int j = 0; j < 8; j++) {
                        acc[j][0] += v00 * wv[j];
                        acc[j][1] += v01 * wv[j];
                        acc[j][2] += v10 * wv[j];
                        acc[j][3] += v11 * wv[j];
                    }
                }
            }
        }
        __syncthreads();
    }

    if (tid >= 441) return;
    #pragma unroll
    for (int j = 0; j < 8; j++) {
        int co = coB + j;
        float m = fmaxf(fmaxf(acc[j][0], acc[j][1]), fmaxf(acc[j][2], acc[j][3]));
        m = fmaxf(m + bias[co], 0.0f);
        g_e2p[((size_t)n * 128 + co) * E2S + (ty + 1) * 23 + (tx + 1)] = m;
    }
}

// ---------------------------------------------------------------------------
// enc3: conv3x3 128->256 + bias + relu @21x21.  CC=16, dynamic smem (53KB),
// 8 chunks. 448 threads, 1 px x 32 couts.
// ---------------------------------------------------------------------------
#define ENC3_CC 16
__global__ void __launch_bounds__(448) k_enc3(
    const float* __restrict__ w, const float* __restrict__ bias)
{
    extern __shared__ float smem[];
    float* s_in = smem;                       // ENC3_CC * E2S
    float* s_w  = smem + ENC3_CC * E2S;       // ENC3_CC * 288

    const int coB = blockIdx.x * 32;
    const int n   = blockIdx.y;
    const int tid = threadIdx.x;
    const int y = tid / 21, x = tid % 21;

    float acc[32];
    #pragma unroll
    for (int j = 0; j < 32; j++) acc[j] = 0.0f;

    for (int cc = 0; cc < 128; cc += ENC3_CC) {
        const float4* src4 = (const float4*)&g_e2p[((size_t)n * 128 + cc) * E2S];
        float4* dst4 = (float4*)s_in;
        #pragma unroll 1
        for (int idx = tid; idx < ENC3_CC * (E2S / 4); idx += 448) dst4[idx] = src4[idx];
        for (int idx = tid; idx < ENC3_CC * 288; idx += 448) {
            int ci = idx / 288; int k = (idx % 288) / 32; int co = idx % 32;
            s_w[idx] = w[((size_t)(coB + co) * 128 + (cc + ci)) * 9 + k];
        }
        __syncthreads();
        if (tid < 441) {
            #pragma unroll
            for (int ci = 0; ci < ENC3_CC; ci++) {
                const float* si = &s_in[ci * E2S + y * 23 + x];
                float v[9];
                #pragma unroll
                for (int r = 0; r < 3; r++) {
                    v[r*3+0] = si[r*23+0]; v[r*3+1] = si[r*23+1]; v[r*3+2] = si[r*23+2];
                }
                #pragma unroll
                for (int k = 0; k < 9; k++) {
                    float vv = v[k];
                    const float* wb = &s_w[(ci * 9 + k) * 32];
                    #pragma unroll
                    for (int q = 0; q < 8; q++) {
                        float4 wq = *(const float4*)(wb + q * 4);
                        acc[q*4+0] += vv * wq.x;
                        acc[q*4+1] += vv * wq.y;
                        acc[q*4+2] += vv * wq.z;
                        acc[q*4+3] += vv * wq.w;
                    }
                }
            }
        }
        __syncthreads();
    }

    if (tid >= 441) return;
    #pragma unroll
    for (int j = 0; j < 32; j++) {
        int co = coB + j;
        g_feat[((size_t)n * 256 + co) * NP2 + tid] = fmaxf(acc[j] + bias[co], 0.0f);
    }
}

// ---------------------------------------------------------------------------
// depthwise conv 3x3 — feat half (ch 0..255), ALL frames
// ---------------------------------------------------------------------------
__global__ void __launch_bounds__(448) k_dw_feat(const float* __restrict__ dww)
{
    __shared__ float s[NP2];
    const int ch  = blockIdx.x;
    const int n   = blockIdx.y;
    const int tid = threadIdx.x;

    const float* src = &g_feat[((size_t)n * 256 + ch) * NP2];
    if (tid < NP2) s[tid] = src[tid];
    __syncthreads();
    if (tid >= NP2) return;

    float wr[9];
    #pragma unroll
    for (int k = 0; k < 9; k++) wr[k] = __ldg(&dww[(size_t)ch * 9 + k]);

    int y = tid / 21, x = tid % 21;
    float acc = 0.0f;
    #pragma unroll
    for (int k = 0; k < 9; k++) {
        int iy = y + k / 3 - 1, ix = x + k % 3 - 1;
        if (iy >= 0 && iy < 21 && ix >= 0 && ix < 21)
            acc += s[iy * 21 + ix] * wr[k];
    }
    g_gdwf[((size_t)n * 256 + ch) * GWS + tid] = acc;
}

// depthwise conv — h half (ch 256..511), per step
__global__ void __launch_bounds__(448) k_dw_h(const float* __restrict__ dww)
{
    __shared__ float s[NP2];
    const int ch  = blockIdx.x;
    const int b   = blockIdx.y;
    const int tid = threadIdx.x;

    const float* src = &g_h[((size_t)b * HD + ch) * NP2];
    if (tid < NP2) s[tid] = src[tid];
    __syncthreads();
    if (tid >= NP2) return;

    float wr[9];
    #pragma unroll
    for (int k = 0; k < 9; k++) wr[k] = __ldg(&dww[(size_t)(256 + ch) * 9 + k]);

    int y = tid / 21, x = tid % 21;
    float acc = 0.0f;
    #pragma unroll
    for (int k = 0; k < 9; k++) {
        int iy = y + k / 3 - 1, ix = x + k % 3 - 1;
        if (iy >= 0 && iy < 21 && ix >= 0 && ix < 21)
            acc += s[iy * 21 + ix] * wr[k];
    }
    g_gdwh[((size_t)b * 256 + ch) * GWS + tid] = acc;
}

// ---------------------------------------------------------------------------
// pointwise 1x1 512->1024 + bias + LSTM gates.  CC=32, dynamic smem (61.4KB),
// 16 chunks.  grid (32, 8).
// ---------------------------------------------------------------------------
#define PW_CC 32
__global__ void __launch_bounds__(448) k_pw_gates(
    const float* __restrict__ pww, const float* __restrict__ pwb, int t)
{
    extern __shared__ float smem[];
    float* s_in = smem;                       // PW_CC * GWS
    float* s_w  = smem + PW_CC * GWS;         // PW_CC * 32

    const int coB = blockIdx.x * 8;
    const int b   = blockIdx.y;
    const int tid = threadIdx.x;

    float acc[32];
    #pragma unroll
    for (int j = 0; j < 32; j++) acc[j] = 0.0f;

    for (int cc = 0; cc < 512; cc += PW_CC) {
        const float* src = (cc < 256)
            ? &g_gdwf[((size_t)(b * TT + t) * 256 + cc) * GWS]
            : &g_gdwh[((size_t)b * 256 + (cc - 256)) * GWS];
        const float4* src4 = (const float4*)src;
        float4* dst4 = (float4*)s_in;
        #pragma unroll 1
        for (int idx = tid; idx < PW_CC * (GWS / 4); idx += 448) dst4[idx] = src4[idx];
        for (int idx = tid; idx < PW_CC * 32; idx += 448) {
            int ci = idx >> 5, j = idx & 31;
            int gate = j >> 3, co = j & 7;
            s_w[idx] = pww[((size_t)(gate * 256 + coB + co)) * 512 + cc + ci];
        }
        __syncthreads();
        if (tid < NP2) {
            #pragma unroll
            for (int ci = 0; ci < PW_CC; ci++) {
                float v = s_in[ci * GWS + tid];
                const float* fw = &s_w[ci * 32];
                #pragma unroll
                for (int q = 0; q < 8; q++) {
                    float4 wq = *(const float4*)(fw + q * 4);
                    acc[q*4+0] += v * wq.x;
                    acc[q*4+1] += v * wq.y;
                    acc[q*4+2] += v * wq.z;
                    acc[q*4+3] += v * wq.w;
                }
            }
        }
        __syncthreads();
    }

    if (tid >= NP2) return;
    const int n = b * TT + t;
    const int y = tid / 21, x = tid % 21;
    const int padpix = (y + 1) * 23 + (x + 1);
    #pragma unroll
    for (int co = 0; co < 8; co++) {
        int cg = coB + co;
        float iv = sigm(acc[co]       + pwb[cg]);
        float fv = sigm(acc[8 + co]   + pwb[256 + cg]);
        float ov = sigm(acc[16 + co]  + pwb[512 + cg]);
        float gv = tanhf(acc[24 + co] + pwb[768 + cg]);
        size_t off = ((size_t)b * HD + cg) * NP2 + tid;
        float c2 = fv * g_c[off] + iv * gv;
        float h2 = ov * tanhf(c2);
        g_c[off] = c2;
        g_h[off] = h2;
        g_hsp[((size_t)n * 256 + cg) * E2S + padpix] = h2;
    }
}

// ---------------------------------------------------------------------------
// dec1: folded up2+conv3x3 256->128 @21->42.  CC=16 static (43KB), 16 chunks.
// ---------------------------------------------------------------------------
#define D1_CC 16
__global__ void __launch_bounds__(448) k_dec1(
    const float* __restrict__ w, const float* __restrict__ bias)
{
    __shared__ __align__(16) float s_in[D1_CC * E2S];
    __shared__ __align__(16) float s_fw[D1_CC * 128];

    const int coB = blockIdx.x * 8;
    const int n   = blockIdx.y;
    const int tid = threadIdx.x;
    const int ty = tid / 21, tx = tid % 21;

    float acc[8][4];
    #pragma unroll
    for (int j = 0; j < 8; j++) { acc[j][0]=acc[j][1]=acc[j][2]=acc[j][3]=0.f; }

    for (int cc = 0; cc < 256; cc += D1_CC) {
        const float4* src4 = (const float4*)&g_hsp[((size_t)n * 256 + cc) * E2S];
        float4* dst4 = (float4*)s_in;
        #pragma unroll 1
        for (int idx = tid; idx < D1_CC * (E2S / 4); idx += 448) dst4[idx] = src4[idx];
        for (int idx = tid; idx < D1_CC * 128; idx += 448) {
            int ci = idx >> 7;
            int pt = (idx >> 3) & 15;
            int co = idx & 7;
            int par = pt >> 2, tap = pt & 3;
            int py = par >> 1, px = par & 1, a = tap >> 1, b = tap & 1;
            const float* wb = &w[((size_t)(coB + co) * 256 + cc + ci) * 9];
            int rlo, rhi, clo, chi;
            if (py == 0) { if (a == 0) { rlo = 0; rhi = 0; } else { rlo = 1; rhi = 2; } }
            else         { if (a == 0) { rlo = 0; rhi = 1; } else { rlo = 2; rhi = 2; } }
            if (px == 0) { if (b == 0) { clo = 0; chi = 0; } else { clo = 1; chi = 2; } }
            else         { if (b == 0) { clo = 0; chi = 1; } else { clo = 2; chi = 2; } }
            float s = 0.0f;
            for (int r = rlo; r <= rhi; r++)
                for (int c = clo; c <= chi; c++)
                    s += wb[r * 3 + c];
            s_fw[idx] = s;
        }
        __syncthreads();
        if (tid < 441) {
            #pragma unroll
            for (int ci = 0; ci < D1_CC; ci++) {
                const float* si = &s_in[ci * E2S + ty * 23 + tx];
                float v[3][3];
                #pragma unroll
                for (int r = 0; r < 3; r++) {
                    v[r][0] = si[r*23+0]; v[r][1] = si[r*23+1]; v[r][2] = si[r*23+2];
                }
                const float* fw = &s_fw[ci * 128];
                #pragma unroll
                for (int par = 0; par < 4; par++) {
                    const int py = par >> 1, px = par & 1;
                    #pragma unroll
                    for (int tap = 0; tap < 4; tap++) {
                        const int a = tap >> 1, b = tap & 1;
                        float vv = v[py + a][px + b];
                        float4 wA = *(const float4*)&fw[(par * 4 + tap) * 8];
                        float4 wB = *(const float4*)&fw[(par * 4 + tap) * 8 + 4];
                        acc[0][par] += vv * wA.x;  acc[1][par] += vv * wA.y;
                        acc[2][par] += vv * wA.z;  acc[3][par] += vv * wA.w;
                        acc[4][par] += vv * wB.x;  acc[5][par] += vv * wB.y;
                        acc[6][par] += vv * wB.z;  acc[7][par] += vv * wB.w;
                    }
                }
            }
        }
        __syncthreads();
    }

    if (tid >= 441) return;
    #pragma unroll
    for (int j = 0; j < 8; j++) {
        int co = coB + j;
        float bv = bias[co];
        #pragma unroll
        for (int py = 0; py < 2; py++) {
            int Y = ty * 2 + py;
            int X = tx * 2;
            float* op = &g_d1p[((size_t)n * 128 + co) * D1S + (Y + 1) * 44 + (X + 1)];
            op[0] = fmaxf(acc[j][py * 2 + 0] + bv, 0.0f);
            op[1] = fmaxf(acc[j][py * 2 + 1] + bv, 0.0f);
        }
    }
}

// ---------------------------------------------------------------------------
// dec2: folded up2+conv3x3 128->64 @42->84.  CC=8, dynamic smem (66KB),
// 16 chunks.  grid (4 tiles, 8 co-groups, BT).
// ---------------------------------------------------------------------------
#define D2_CC 8
__global__ void __launch_bounds__(448) k_dec2(
    const float* __restrict__ w, const float* __restrict__ bias)
{
    extern __shared__ float smem[];
    float* s_in = smem;                       // D2_CC * D1S
    float* s_fw = smem + D2_CC * D1S;         // D2_CC * 128

    const int n   = blockIdx.z;
    const int coB = blockIdx.y * 8;
    const int tY  = blockIdx.x >> 1;
    const int tX  = blockIdx.x & 1;
    const int y0  = tY * 21, x0 = tX * 21;
    const int tid = threadIdx.x;
    const int ty = tid / 21, tx = tid % 21;

    float acc[8][4];
    #pragma unroll
    for (int j = 0; j < 8; j++) { acc[j][0]=acc[j][1]=acc[j][2]=acc[j][3]=0.f; }

    for (int cc = 0; cc < 128; cc += D2_CC) {
        const float4* src4 = (const float4*)&g_d1p[((size_t)n * 128 + cc) * D1S];
        float4* dst4 = (float4*)s_in;
        #pragma unroll 1
        for (int idx = tid; idx < D2_CC * (D1S / 4); idx += 448) dst4[idx] = src4[idx];
        for (int idx = tid; idx < D2_CC * 128; idx += 448) {
            int ci = idx >> 7;
            int pt = (idx >> 3) & 15;
            int co = idx & 7;
            int par = pt >> 2, tap = pt & 3;
            int py = par >> 1, px = par & 1, a = tap >> 1, b = tap & 1;
            const float* wb = &w[((size_t)(coB + co) * 128 + cc + ci) * 9];
            int rlo, rhi, clo, chi;
            if (py == 0) { if (a == 0) { rlo = 0; rhi = 0; } else { rlo = 1; rhi = 2; } }
            else         { if (a == 0) { rlo = 0; rhi = 1; } else { rlo = 2; rhi = 2; } }
            if (px == 0) { if (b == 0) { clo = 0; chi = 0; } else { clo = 1; chi = 2; } }
            else         { if (b == 0) { clo = 0; chi = 1; } else { clo = 2; chi = 2; } }
            float s = 0.0f;
            for (int r = rlo; r <= rhi; r++)
                for (int c = clo; c <= chi; c++)
                    s += wb[r * 3 + c];
            s_fw[idx] = s;
        }
        __syncthreads();
        if (tid < 441) {
            #pragma unroll
            for (int ci = 0; ci < D2_CC; ci++) {
                const float* si = &s_in[ci * D1S + (y0 + ty) * 44 + (x0 + tx)];
                float v[3][3];
                #pragma unroll
                for (int r = 0; r < 3; r++) {
                    v[r][0] = si[r*44+0]; v[r][1] = si[r*44+1]; v[r][2] = si[r*44+2];
                }
                const float* fw = &s_fw[ci * 128];
                #pragma unroll
                for (int par = 0; par < 4; par++) {
                    const int py = par >> 1, px = par & 1;
                    #pragma unroll
                    for (int tap = 0; tap < 4; tap++) {
                        const int a = tap >> 1, b = tap & 1;
                        float vv = v[py + a][px + b];
                        float4 wA = *(const float4*)&fw[(par * 4 + tap) * 8];
                        float4 wB = *(const float4*)&fw[(par * 4 + tap) * 8 + 4];
                        acc[0][par] += vv * wA.x;  acc[1][par] += vv * wA.y;
                        acc[2][par] += vv * wA.z;  acc[3][par] += vv * wA.w;
                        acc[4][par] += vv * wB.x;  acc[5][par] += vv * wB.y;
                        acc[6][par] += vv * wB.z;  acc[7][par] += vv * wB.w;
                    }
                }
            }
        }
        __syncthreads();
    }

    if (tid >= 441) return;
    #pragma unroll
    for (int j = 0; j < 8; j++) {
        int co = coB + j;
        float bv = bias[co];
        #pragma unroll
        for (int py = 0; py < 2; py++) {
            int Y = (y0 + ty) * 2 + py;
            int X = (x0 + tx) * 2;
            float2 o;
            o.x = fmaxf(acc[j][py * 2 + 0] + bv, 0.0f);
            o.y = fmaxf(acc[j][py * 2 + 1] + bv, 0.0f);
            *(float2*)&g_d2[((size_t)n * 64 + co) * NP0 + Y * 84 + X] = o;
        }
    }
}

// ---------------------------------------------------------------------------
// dec3: 1x1 conv 64->1 + bias.
// ---------------------------------------------------------------------------
__global__ void k_dec3(const float* __restrict__ w, const float* __restrict__ bias,
                       float* __restrict__ out)
{
    __shared__ float s_w[64];
    if (threadIdx.x < 64) s_w[threadIdx.x] = w[threadIdx.x];
    __syncthreads();

    int idx = blockIdx.x * blockDim.x + threadIdx.x;
    if (idx >= OUTN) return;
    int n = idx / NP0, pix = idx % NP0;
    const float* d = &g_d2[(size_t)n * 64 * NP0 + pix];
    float acc = bias[0];
    #pragma unroll
    for (int c = 0; c < 64; c++) acc += d[(size_t)c * NP0] * s_w[c];
    out[idx] = acc;
}

__global__ void k_copy_hc(float* __restrict__ out)
{
    int i = blockIdx.x * blockDim.x + threadIdx.x;
    if (i < BB * HD * NP2) {
        out[OUTN + i]     = g_h[i];
        out[2 * OUTN + i] = g_c[i];
    }
}

// ---------------------------------------------------------------------------
extern "C" void kernel_launch(void* const* d_in, const int* in_sizes, int n_in,
                              void* d_out, int out_size)
{
    const float* x      = (const float*)d_in[0];
    const float* enc_w1 = (const float*)d_in[1];
    const float* enc_b1 = (const float*)d_in[2];
    const float* enc_w2 = (const float*)d_in[3];
    const float* enc_b2 = (const float*)d_in[4];
    const float* enc_w3 = (const float*)d_in[5];
    const float* enc_b3 = (const float*)d_in[6];
    const float* dw_w   = (const float*)d_in[7];
    const float* pw_w   = (const float*)d_in[8];
    const float* pw_b   = (const float*)d_in[9];
    const float* dec_w1 = (const float*)d_in[10];
    const float* dec_b1 = (const float*)d_in[11];
    const float* dec_w2 = (const float*)d_in[12];
    const float* dec_b2 = (const float*)d_in[13];
    const float* dec_w3 = (const float*)d_in[14];
    const float* dec_b3 = (const float*)d_in[15];
    float* out = (float*)d_out;

    float *e1p, *e2p, *hsp, *d1p;
    cudaGetSymbolAddress((void**)&e1p, g_e1p);
    cudaGetSymbolAddress((void**)&e2p, g_e2p);
    cudaGetSymbolAddress((void**)&hsp, g_hsp);
    cudaGetSymbolAddress((void**)&d1p, g_d1p);

    // dynamic smem opt-in (idempotent)
    const int enc2_smem = (ENC2_CC * E1S + ENC2_CC * 72)  * 4;
    const int enc3_smem = (ENC3_CC * E2S + ENC3_CC * 288) * 4;
    const int pw_smem   = (PW_CC   * GWS + PW_CC   * 32)  * 4;
    const int d2_smem   = (D2_CC   * D1S + D2_CC   * 128) * 4;
    cudaFuncSetAttribute(k_enc2,     cudaFuncAttributeMaxDynamicSharedMemorySize, enc2_smem);
    cudaFuncSetAttribute(k_enc3,     cudaFuncAttributeMaxDynamicSharedMemorySize, enc3_smem);
    cudaFuncSetAttribute(k_pw_gates, cudaFuncAttributeMaxDynamicSharedMemorySize, pw_smem);
    cudaFuncSetAttribute(k_dec2,     cudaFuncAttributeMaxDynamicSharedMemorySize, d2_smem);

    // zero state + borders (interiors are rewritten every call)
    k_zero_hc<<<(BB * HD * NP2 + 255) / 256, 256>>>();
    k_border<<<BT * 64, 64>>>(e1p, E1S, 44, 44);

    // encoder
    k_enc1<<<dim3(4, 1, BT), 448>>>(x, enc_w1, enc_b1);
    k_border<<<BT * 128, 64>>>(e2p, E2S, 23, 23);
    k_enc2<<<dim3(1, 128 / 8, BT), 448, enc2_smem>>>(enc_w2, enc_b2);
    k_enc3<<<dim3(256 / 32, BT), 448, enc3_smem>>>(enc_w3, enc_b3);

    // h-independent depthwise(feat), all frames
    k_border<<<BT * 256, 64>>>(hsp, E2S, 23, 23);
    k_dw_feat<<<dim3(256, BT), 448>>>(dw_w);

    // ConvLSTM over T=16 steps
    for (int t = 0; t < TT; t++) {
        k_dw_h<<<dim3(256, BB), 448>>>(dw_w);
        k_pw_gates<<<dim3(32, BB), 448, pw_smem>>>(pw_w, pw_b, t);
    }

    // decoder (folded nearest-upsample convs)
    k_border<<<BT * 128, 64>>>(d1p, D1S, 44, 44);
    k_dec1<<<dim3(128 / 8, BT), 448>>>(dec_w1, dec_b1);
    k_dec2<<<dim3(4, 64 / 8, BT), 448, d2_smem>>>(dec_w2, dec_b2);
    k_dec3<<<(OUTN + 255) / 256, 256>>>(dec_w3, dec_b3, out);

    if (out_size >= 3 * OUTN)
        k_copy_hc<<<(BB * HD * NP2 + 255) / 256, 256>>>(out);
}

// round 10
// speedup vs baseline: 1.0006x; 1.0006x over previous
#include <cuda_runtime.h>
#include <cuda_bf16.h>
#include <math.h>

// ---------------------------------------------------------------------------
//   x: (8,16,3,84,84)  B=8 T=16  -> BT=128 frames
//   enc: 3->64 (pool), 64->128 (pool), 128->256    @84/42/21
//   ConvLSTM: depthwise 3x3 g=512, pointwise 512->1024, gates
//   dec: up2 conv 256->128 @42, up2 conv 128->64 @84, 1x1 64->1
//   Halo-padded buffers; smem fills are linear float4 copies.
//   Big kernels use dynamic smem (>48KB) to halve K-chunk count.
// ---------------------------------------------------------------------------

#define BT   128
#define BB   8
#define TT   16
#define HD   256
#define NP2  441
#define NP0  7056
#define OUTN 903168

#define E1S  1936   // 44*44 padded channel (42x42 interior)
#define E2S  544    // 23*23=529 padded to 544 (21x21 interior)
#define GWS  448    // 441 padded to 448
#define D1S  1936   // 44*44 padded channel (42x42 interior)

__device__ float g_e1p [(size_t)BT * 64  * E1S];
__device__ float g_e2p [(size_t)BT * 128 * E2S];
__device__ float g_feat[(size_t)BT * 256 * NP2];
__device__ float g_gdwf[(size_t)BT * 256 * GWS];
__device__ float g_gdwh[(size_t)BB * 256 * GWS];
__device__ float g_hsp [(size_t)BT * 256 * E2S];
__device__ float g_d1p [(size_t)BT * 128 * D1S];
__device__ float g_d2  [(size_t)BT * 64  * NP0];
__device__ float g_h   [BB * HD * NP2];
__device__ float g_c   [BB * HD * NP2];

__device__ __forceinline__ float sigm(float x) { return 1.0f / (1.0f + expf(-x)); }

// zero only the halo border + stride tail of padded channels.
// grid = #channels, block = 64.
__global__ void k_border(float* buf, int S, int W2, int H2)
{
    float* ch = buf + (size_t)blockIdx.x * S;
    const int nside = H2 - 2;
    const int nb = 2 * W2 + 2 * nside + (S - W2 * H2);
    for (int i = threadIdx.x; i < nb; i += 64) {
        int pos;
        if (i < W2)                       pos = i;
        else if (i < 2 * W2)              pos = (H2 - 1) * W2 + (i - W2);
        else if (i < 2 * W2 + nside)      pos = (i - 2 * W2 + 1) * W2;
        else if (i < 2 * W2 + 2 * nside)  pos = (i - 2 * W2 - nside + 1) * W2 + (W2 - 1);
        else                              pos = W2 * H2 + (i - 2 * W2 - 2 * nside);
        ch[pos] = 0.0f;
    }
}

__global__ void k_zero_hc()
{
    int i = blockIdx.x * blockDim.x + threadIdx.x;
    if (i < BB * HD * NP2) { g_h[i] = 0.0f; g_c[i] = 0.0f; }
}

// ---------------------------------------------------------------------------
// enc1: conv3x3 3->64 + bias + relu + maxpool2.  84x84 -> 42x42 into e1p pad.
// ---------------------------------------------------------------------------
__global__ void __launch_bounds__(448) k_enc1(
    const float* __restrict__ x, const float* __restrict__ w,
    const float* __restrict__ bias)
{
    __shared__ float s_in[3 * 44 * 44];
    __shared__ __align__(16) float s_w[3 * 9 * 64];

    const int n   = blockIdx.z;
    const int bx  = blockIdx.x;
    const int py0 = (bx >> 1) * 21;
    const int px0 = (bx & 1) * 21;
    const int oy0 = py0 * 2;
    const int ox0 = px0 * 2;
    const int tid = threadIdx.x;

    const float* xn = x + (size_t)n * 3 * NP0;

    for (int idx = tid; idx < 3 * 44 * 44; idx += 448) {
        int ci = idx / 1936, rem = idx % 1936;
        int r = rem / 44, c = rem % 44;
        int gy = oy0 - 1 + r, gx = ox0 - 1 + c;
        float v = 0.0f;
        if (gy >= 0 && gy < 84 && gx >= 0 && gx < 84)
            v = xn[(size_t)ci * NP0 + gy * 84 + gx];
        s_in[idx] = v;
    }
    for (int idx = tid; idx < 3 * 9 * 64; idx += 448) {
        int ci = idx / (9 * 64); int k = (idx % (9 * 64)) / 64; int co = idx % 64;
        s_w[idx] = w[((size_t)co * 3 + ci) * 9 + k];
    }
    __syncthreads();
    if (tid >= 441) return;

    const int ty = tid / 21, tx = tid % 21;
    const int by = 2 * ty, bxp = 2 * tx;

    for (int cg = 0; cg < 8; cg++) {
        float acc[8][4];
        #pragma unroll
        for (int j = 0; j < 8; j++) { acc[j][0]=acc[j][1]=acc[j][2]=acc[j][3]=0.f; }
        #pragma unroll
        for (int ci = 0; ci < 3; ci++) {
            const float* si = &s_in[ci * 1936];
            #pragma unroll
            for (int k = 0; k < 9; k++) {
                int dy = k / 3, dx = k % 3;
                const float* p0 = si + (by + dy) * 44 + (bxp + dx);
                float v00 = p0[0], v01 = p0[1], v10 = p0[44], v11 = p0[45];
                float4 wA = *(const float4*)&s_w[(ci * 9 + k) * 64 + cg * 8];
                float4 wB = *(const float4*)&s_w[(ci * 9 + k) * 64 + cg * 8 + 4];
                float wv[8] = {wA.x, wA.y, wA.z, wA.w, wB.x, wB.y, wB.z, wB.w};
                #pragma unroll
                for (int j = 0; j < 8; j++) {
                    acc[j][0] += v00 * wv[j];
                    acc[j][1] += v01 * wv[j];
                    acc[j][2] += v10 * wv[j];
                    acc[j][3] += v11 * wv[j];
                }
            }
        }
        #pragma unroll
        for (int j = 0; j < 8; j++) {
            int co = cg * 8 + j;
            float m = fmaxf(fmaxf(acc[j][0], acc[j][1]), fmaxf(acc[j][2], acc[j][3]));
            m = fmaxf(m + bias[co], 0.0f);
            g_e1p[((size_t)n * 64 + co) * E1S + (py0 + ty + 1) * 44 + (px0 + tx + 1)] = m;
        }
    }
}

// ---------------------------------------------------------------------------
// enc2: conv3x3 64->128 + bias + relu + maxpool2 @42 -> 21 into e2p pad.
// CC=8, dynamic smem (64.3KB), 8 chunks.
// ---------------------------------------------------------------------------
#define ENC2_CC 8
__global__ void __launch_bounds__(448) k_enc2(
    const float* __restrict__ w, const float* __restrict__ bias)
{
    extern __shared__ float smem[];
    float* s_in = smem;                       // ENC2_CC * E1S
    float* s_w  = smem + ENC2_CC * E1S;       // ENC2_CC * 72

    const int n   = blockIdx.z;
    const int coB = blockIdx.y * 8;
    const int tid = threadIdx.x;
    const int ty = tid / 21, tx = tid % 21;
    const int by = 2 * ty, bxp = 2 * tx;

    float acc[8][4];
    #pragma unroll
    for (int j = 0; j < 8; j++) { acc[j][0]=acc[j][1]=acc[j][2]=acc[j][3]=0.f; }

    for (int cc = 0; cc < 64; cc += ENC2_CC) {
        const float4* src4 = (const float4*)&g_e1p[((size_t)n * 64 + cc) * E1S];
        float4* dst4 = (float4*)s_in;
        #pragma unroll 1
        for (int idx = tid; idx < ENC2_CC * (E1S / 4); idx += 448) dst4[idx] = src4[idx];
        for (int idx = tid; idx < ENC2_CC * 72; idx += 448) {
            int ci = idx / 72; int k = (idx % 72) / 8; int co = idx % 8;
            s_w[idx] = w[((size_t)(coB + co) * 64 + (cc + ci)) * 9 + k];
        }
        __syncthreads();
        if (tid < 441) {
            #pragma unroll
            for (int ci = 0; ci < ENC2_CC; ci++) {
                const float* si = &s_in[ci * E1S];
                #pragma unroll
                for (int k = 0; k < 9; k++) {
                    int dy = k / 3, dx = k % 3;
                    const float* p0 = si + (by + dy) * 44 + (bxp + dx);
                    float v00 = p0[0], v01 = p0[1], v10 = p0[44], v11 = p0[45];
                    float4 wA = *(const float4*)&s_w[(ci * 9 + k) * 8];
                    float4 wB = *(const float4*)&s_w[(ci * 9 + k) * 8 + 4];
                    float wv[8] = {wA.x, wA.y, wA.z, wA.w, wB.x, wB.y, wB.z, wB.w};
                    #pragma unroll
                    for (int j = 0; j < 8; j++) {
                        acc[j][0] += v00 * wv[j];
                        acc[j][1] += v01 * wv[j];
                        acc[j][2] += v10 * wv[j];
                        acc[j][3] += v11 * wv[j];
                    }
                }
            }
        }
        __syncthreads();
    }

    if (tid >= 441) return;
    #pragma unroll
    for (int j = 0; j < 8; j++) {
        int co = coB + j;
        float m = fmaxf(fmaxf(acc[j][0], acc[j][1]), fmaxf(acc[j][2], acc[j][3]));
        m = fmaxf(m + bias[co], 0.0f);
        g_e2p[((size_t)n * 128 + co) * E2S + (ty + 1) * 23 + (tx + 1)] = m;
    }
}

// ---------------------------------------------------------------------------
// enc3: conv3x3 128->256 + bias + relu @21x21.  CC=16, dynamic smem (53KB),
// 8 chunks. 448 threads, 1 px x 32 couts.
// ---------------------------------------------------------------------------
#define ENC3_CC 16
__global__ void __launch_bounds__(448) k_enc3(
    const float* __restrict__ w, const float* __restrict__ bias)
{
    extern __shared__ float smem[];
    float* s_in = smem;                       // ENC3_CC * E2S
    float* s_w  = smem + ENC3_CC * E2S;       // ENC3_CC * 288

    const int coB = blockIdx.x * 32;
    const int n   = blockIdx.y;
    const int tid = threadIdx.x;
    const int y = tid / 21, x = tid % 21;

    float acc[32];
    #pragma unroll
    for (int j = 0; j < 32; j++) acc[j] = 0.0f;

    for (int cc = 0; cc < 128; cc += ENC3_CC) {
        const float4* src4 = (const float4*)&g_e2p[((size_t)n * 128 + cc) * E2S];
        float4* dst4 = (float4*)s_in;
        #pragma unroll 1
        for (int idx = tid; idx < ENC3_CC * (E2S / 4); idx += 448) dst4[idx] = src4[idx];
        for (int idx = tid; idx < ENC3_CC * 288; idx += 448) {
            int ci = idx / 288; int k = (idx % 288) / 32; int co = idx % 32;
            s_w[idx] = w[((size_t)(coB + co) * 128 + (cc + ci)) * 9 + k];
        }
        __syncthreads();
        if (tid < 441) {
            #pragma unroll
            for (int ci = 0; ci < ENC3_CC; ci++) {
                const float* si = &s_in[ci * E2S + y * 23 + x];
                float v[9];
                #pragma unroll
                for (int r = 0; r < 3; r++) {
                    v[r*3+0] = si[r*23+0]; v[r*3+1] = si[r*23+1]; v[r*3+2] = si[r*23+2];
                }
                #pragma unroll
                for (int k = 0; k < 9; k++) {
                    float vv = v[k];
                    const float* wb = &s_w[(ci * 9 + k) * 32];
                    #pragma unroll
                    for (int q = 0; q < 8; q++) {
                        float4 wq = *(const float4*)(wb + q * 4);
                        acc[q*4+0] += vv * wq.x;
                        acc[q*4+1] += vv * wq.y;
                        acc[q*4+2] += vv * wq.z;
                        acc[q*4+3] += vv * wq.w;
                    }
                }
            }
        }
        __syncthreads();
    }

    if (tid >= 441) return;
    #pragma unroll
    for (int j = 0; j < 32; j++) {
        int co = coB + j;
        g_feat[((size_t)n * 256 + co) * NP2 + tid] = fmaxf(acc[j] + bias[co], 0.0f);
    }
}

// ---------------------------------------------------------------------------
// depthwise conv 3x3 — feat half (ch 0..255), ALL frames
// ---------------------------------------------------------------------------
__global__ void __launch_bounds__(448) k_dw_feat(const float* __restrict__ dww)
{
    __shared__ float s[NP2];
    const int ch  = blockIdx.x;
    const int n   = blockIdx.y;
    const int tid = threadIdx.x;

    const float* src = &g_feat[((size_t)n * 256 + ch) * NP2];
    if (tid < NP2) s[tid] = src[tid];
    __syncthreads();
    if (tid >= NP2) return;

    float wr[9];
    #pragma unroll
    for (int k = 0; k < 9; k++) wr[k] = __ldg(&dww[(size_t)ch * 9 + k]);

    int y = tid / 21, x = tid % 21;
    float acc = 0.0f;
    #pragma unroll
    for (int k = 0; k < 9; k++) {
        int iy = y + k / 3 - 1, ix = x + k % 3 - 1;
        if (iy >= 0 && iy < 21 && ix >= 0 && ix < 21)
            acc += s[iy * 21 + ix] * wr[k];
    }
    g_gdwf[((size_t)n * 256 + ch) * GWS + tid] = acc;
}

// depthwise conv — h half (ch 256..511), per step
__global__ void __launch_bounds__(448) k_dw_h(const float* __restrict__ dww)
{
    __shared__ float s[NP2];
    const int ch  = blockIdx.x;
    const int b   = blockIdx.y;
    const int tid = threadIdx.x;

    const float* src = &g_h[((size_t)b * HD + ch) * NP2];
    if (tid < NP2) s[tid] = src[tid];
    __syncthreads();
    if (tid >= NP2) return;

    float wr[9];
    #pragma unroll
    for (int k = 0; k < 9; k++) wr[k] = __ldg(&dww[(size_t)(256 + ch) * 9 + k]);

    int y = tid / 21, x = tid % 21;
    float acc = 0.0f;
    #pragma unroll
    for (int k = 0; k < 9; k++) {
        int iy = y + k / 3 - 1, ix = x + k % 3 - 1;
        if (iy >= 0 && iy < 21 && ix >= 0 && ix < 21)
            acc += s[iy * 21 + ix] * wr[k];
    }
    g_gdwh[((size_t)b * 256 + ch) * GWS + tid] = acc;
}

// ---------------------------------------------------------------------------
// pointwise 1x1 512->1024 + bias + LSTM gates.  CC=32, dynamic smem (61.4KB),
// 16 chunks.  grid (32, 8).
// ---------------------------------------------------------------------------
#define PW_CC 32
__global__ void __launch_bounds__(448) k_pw_gates(
    const float* __restrict__ pww, const float* __restrict__ pwb, int t)
{
    extern __shared__ float smem[];
    float* s_in = smem;                       // PW_CC * GWS
    float* s_w  = smem + PW_CC * GWS;         // PW_CC * 32

    const int coB = blockIdx.x * 8;
    const int b   = blockIdx.y;
    const int tid = threadIdx.x;

    float acc[32];
    #pragma unroll
    for (int j = 0; j < 32; j++) acc[j] = 0.0f;

    for (int cc = 0; cc < 512; cc += PW_CC) {
        const float* src = (cc < 256)
            ? &g_gdwf[((size_t)(b * TT + t) * 256 + cc) * GWS]
            : &g_gdwh[((size_t)b * 256 + (cc - 256)) * GWS];
        const float4* src4 = (const float4*)src;
        float4* dst4 = (float4*)s_in;
        #pragma unroll 1
        for (int idx = tid; idx < PW_CC * (GWS / 4); idx += 448) dst4[idx] = src4[idx];
        for (int idx = tid; idx < PW_CC * 32; idx += 448) {
            int ci = idx >> 5, j = idx & 31;
            int gate = j >> 3, co = j & 7;
            s_w[idx] = pww[((size_t)(gate * 256 + coB + co)) * 512 + cc + ci];
        }
        __syncthreads();
        if (tid < NP2) {
            #pragma unroll
            for (int ci = 0; ci < PW_CC; ci++) {
                float v = s_in[ci * GWS + tid];
                const float* fw = &s_w[ci * 32];
                #pragma unroll
                for (int q = 0; q < 8; q++) {
                    float4 wq = *(const float4*)(fw + q * 4);
                    acc[q*4+0] += v * wq.x;
                    acc[q*4+1] += v * wq.y;
                    acc[q*4+2] += v * wq.z;
                    acc[q*4+3] += v * wq.w;
                }
            }
        }
        __syncthreads();
    }

    if (tid >= NP2) return;
    const int n = b * TT + t;
    const int y = tid / 21, x = tid % 21;
    const int padpix = (y + 1) * 23 + (x + 1);
    #pragma unroll
    for (int co = 0; co < 8; co++) {
        int cg = coB + co;
        float iv = sigm(acc[co]       + pwb[cg]);
        float fv = sigm(acc[8 + co]   + pwb[256 + cg]);
        float ov = sigm(acc[16 + co]  + pwb[512 + cg]);
        float gv = tanhf(acc[24 + co] + pwb[768 + cg]);
        size_t off = ((size_t)b * HD + cg) * NP2 + tid;
        float c2 = fv * g_c[off] + iv * gv;
        float h2 = ov * tanhf(c2);
        g_c[off] = c2;
        g_h[off] = h2;
        g_hsp[((size_t)n * 256 + cg) * E2S + padpix] = h2;
    }
}

// ---------------------------------------------------------------------------
// dec1: folded up2+conv3x3 256->128 @21->42.  CC=16 static (43KB), 16 chunks.
// ---------------------------------------------------------------------------
#define D1_CC 16
__global__ void __launch_bounds__(448) k_dec1(
    const float* __restrict__ w, const float* __restrict__ bias)
{
    __shared__ __align__(16) float s_in[D1_CC * E2S];
    __shared__ __align__(16) float s_fw[D1_CC * 128];

    const int coB = blockIdx.x * 8;
    const int n   = blockIdx.y;
    const int tid = threadIdx.x;
    const int ty = tid / 21, tx = tid % 21;

    float acc[8][4];
    #pragma unroll
    for (int j = 0; j < 8; j++) { acc[j][0]=acc[j][1]=acc[j][2]=acc[j][3]=0.f; }

    for (int cc = 0; cc < 256; cc += D1_CC) {
        const float4* src4 = (const float4*)&g_hsp[((size_t)n * 256 + cc) * E2S];
        float4* dst4 = (float4*)s_in;
        #pragma unroll 1
        for (int idx = tid; idx < D1_CC * (E2S / 4); idx += 448) dst4[idx] = src4[idx];
        for (int idx = tid; idx < D1_CC * 128; idx += 448) {
            int ci = idx >> 7;
            int pt = (idx >> 3) & 15;
            int co = idx & 7;
            int par = pt >> 2, tap = pt & 3;
            int py = par >> 1, px = par & 1, a = tap >> 1, b = tap & 1;
            const float* wb = &w[((size_t)(coB + co) * 256 + cc + ci) * 9];
            int rlo, rhi, clo, chi;
            if (py == 0) { if (a == 0) { rlo = 0; rhi = 0; } else { rlo = 1; rhi = 2; } }
            else         { if (a == 0) { rlo = 0; rhi = 1; } else { rlo = 2; rhi = 2; } }
            if (px == 0) { if (b == 0) { clo = 0; chi = 0; } else { clo = 1; chi = 2; } }
            else         { if (b == 0) { clo = 0; chi = 1; } else { clo = 2; chi = 2; } }
            float s = 0.0f;
            for (int r = rlo; r <= rhi; r++)
                for (int c = clo; c <= chi; c++)
                    s += wb[r * 3 + c];
            s_fw[idx] = s;
        }
        __syncthreads();
        if (tid < 441) {
            #pragma unroll
            for (int ci = 0; ci < D1_CC; ci++) {
                const float* si = &s_in[ci * E2S + ty * 23 + tx];
                float v[3][3];
                #pragma unroll
                for (int r = 0; r < 3; r++) {
                    v[r][0] = si[r*23+0]; v[r][1] = si[r*23+1]; v[r][2] = si[r*23+2];
                }
                const float* fw = &s_fw[ci * 128];
                #pragma unroll
                for (int par = 0; par < 4; par++) {
                    const int py = par >> 1, px = par & 1;
                    #pragma unroll
                    for (int tap = 0; tap < 4; tap++) {
                        const int a = tap >> 1, b = tap & 1;
                        float vv = v[py + a][px + b];
                        float4 wA = *(const float4*)&fw[(par * 4 + tap) * 8];
                        float4 wB = *(const float4*)&fw[(par * 4 + tap) * 8 + 4];
                        acc[0][par] += vv * wA.x;  acc[1][par] += vv * wA.y;
                        acc[2][par] += vv * wA.z;  acc[3][par] += vv * wA.w;
                        acc[4][par] += vv * wB.x;  acc[5][par] += vv * wB.y;
                        acc[6][par] += vv * wB.z;  acc[7][par] += vv * wB.w;
                    }
                }
            }
        }
        __syncthreads();
    }

    if (tid >= 441) return;
    #pragma unroll
    for (int j = 0; j < 8; j++) {
        int co = coB + j;
        float bv = bias[co];
        #pragma unroll
        for (int py = 0; py < 2; py++) {
            int Y = ty * 2 + py;
            int X = tx * 2;
            float* op = &g_d1p[((size_t)n * 128 + co) * D1S + (Y + 1) * 44 + (X + 1)];
            op[0] = fmaxf(acc[j][py * 2 + 0] + bv, 0.0f);
            op[1] = fmaxf(acc[j][py * 2 + 1] + bv, 0.0f);
        }
    }
}

// ---------------------------------------------------------------------------
// dec2: folded up2+conv3x3 128->64 @42->84.  CC=8, dynamic smem (66KB),
// 16 chunks.  grid (4 tiles, 8 co-groups, BT).
// ---------------------------------------------------------------------------
#define D2_CC 8
__global__ void __launch_bounds__(448) k_dec2(
    const float* __restrict__ w, const float* __restrict__ bias)
{
    extern __shared__ float smem[];
    float* s_in = smem;                       // D2_CC * D1S
    float* s_fw = smem + D2_CC * D1S;         // D2_CC * 128

    const int n   = blockIdx.z;
    const int coB = blockIdx.y * 8;
    const int tY  = blockIdx.x >> 1;
    const int tX  = blockIdx.x & 1;
    const int y0  = tY * 21, x0 = tX * 21;
    const int tid = threadIdx.x;
    const int ty = tid / 21, tx = tid % 21;

    float acc[8][4];
    #pragma unroll
    for (int j = 0; j < 8; j++) { acc[j][0]=acc[j][1]=acc[j][2]=acc[j][3]=0.f; }

    for (int cc = 0; cc < 128; cc += D2_CC) {
        const float4* src4 = (const float4*)&g_d1p[((size_t)n * 128 + cc) * D1S];
        float4* dst4 = (float4*)s_in;
        #pragma unroll 1
        for (int idx = tid; idx < D2_CC * (D1S / 4); idx += 448) dst4[idx] = src4[idx];
        for (int idx = tid; idx < D2_CC * 128; idx += 448) {
            int ci = idx >> 7;
            int pt = (idx >> 3) & 15;
            int co = idx & 7;
            int par = pt >> 2, tap = pt & 3;
            int py = par >> 1, px = par & 1, a = tap >> 1, b = tap & 1;
            const float* wb = &w[((size_t)(coB + co) * 128 + cc + ci) * 9];
            int rlo, rhi, clo, chi;
            if (py == 0) { if (a == 0) { rlo = 0; rhi = 0; } else { rlo = 1; rhi = 2; } }
            else         { if (a == 0) { rlo = 0; rhi = 1; } else { rlo = 2; rhi = 2; } }
            if (px == 0) { if (b == 0) { clo = 0; chi = 0; } else { clo = 1; chi = 2; } }
            else         { if (b == 0) { clo = 0; chi = 1; } else { clo = 2; chi = 2; } }
            float s = 0.0f;
            for (int r = rlo; r <= rhi; r++)
                for (int c = clo; c <= chi; c++)
                    s += wb[r * 3 + c];
            s_fw[idx] = s;
        }
        __syncthreads();
        if (tid < 441) {
            #pragma unroll
            for (int ci = 0; ci < D2_CC; ci++) {
                const float* si = &s_in[ci * D1S + (y0 + ty) * 44 + (x0 + tx)];
                float v[3][3];
                #pragma unroll
                for (int r = 0; r < 3; r++) {
                    v[r][0] = si[r*44+0]; v[r][1] = si[r*44+1]; v[r][2] = si[r*44+2];
                }
                const float* fw = &s_fw[ci * 128];
                #pragma unroll
                for (int par = 0; par < 4; par++) {
                    const int py = par >> 1, px = par & 1;
                    #pragma unroll
                    for (int tap = 0; tap < 4; tap++) {
                        const int a = tap >> 1, b = tap & 1;
                        float vv = v[py + a][px + b];
                        float4 wA = *(const float4*)&fw[(par * 4 + tap) * 8];
                        float4 wB = *(const float4*)&fw[(par * 4 + tap) * 8 + 4];
                        acc[0][par] += vv * wA.x;  acc[1][par] += vv * wA.y;
                        acc[2][par] += vv * wA.z;  acc[3][par] += vv * wA.w;
                        acc[4][par] += vv * wB.x;  acc[5][par] += vv * wB.y;
                        acc[6][par] += vv * wB.z;  acc[7][par] += vv * wB.w;
                    }
                }
            }
        }
        __syncthreads();
    }

    if (tid >= 441) return;
    #pragma unroll
    for (int j = 0; j < 8; j++) {
        int co = coB + j;
        float bv = bias[co];
        #pragma unroll
        for (int py = 0; py < 2; py++) {
            int Y = (y0 + ty) * 2 + py;
            int X = (x0 + tx) * 2;
            float2 o;
            o.x = fmaxf(acc[j][py * 2 + 0] + bv, 0.0f);
            o.y = fmaxf(acc[j][py * 2 + 1] + bv, 0.0f);
            *(float2*)&g_d2[((size_t)n * 64 + co) * NP0 + Y * 84 + X] = o;
        }
    }
}

// ---------------------------------------------------------------------------
// dec3: 1x1 conv 64->1 + bias.
// ---------------------------------------------------------------------------
__global__ void k_dec3(const float* __restrict__ w, const float* __restrict__ bias,
                       float* __restrict__ out)
{
    __shared__ float s_w[64];
    if (threadIdx.x < 64) s_w[threadIdx.x] = w[threadIdx.x];
    __syncthreads();

    int idx = blockIdx.x * blockDim.x + threadIdx.x;
    if (idx >= OUTN) return;
    int n = idx / NP0, pix = idx % NP0;
    const float* d = &g_d2[(size_t)n * 64 * NP0 + pix];
    float acc = bias[0];
    #pragma unroll
    for (int c = 0; c < 64; c++) acc += d[(size_t)c * NP0] * s_w[c];
    out[idx] = acc;
}

__global__ void k_copy_hc(float* __restrict__ out)
{
    int i = blockIdx.x * blockDim.x + threadIdx.x;
    if (i < BB * HD * NP2) {
        out[OUTN + i]     = g_h[i];
        out[2 * OUTN + i] = g_c[i];
    }
}

// ---------------------------------------------------------------------------
extern "C" void kernel_launch(void* const* d_in, const int* in_sizes, int n_in,
                              void* d_out, int out_size)
{
    const float* x      = (const float*)d_in[0];
    const float* enc_w1 = (const float*)d_in[1];
    const float* enc_b1 = (const float*)d_in[2];
    const float* enc_w2 = (const float*)d_in[3];
    const float* enc_b2 = (const float*)d_in[4];
    const float* enc_w3 = (const float*)d_in[5];
    const float* enc_b3 = (const float*)d_in[6];
    const float* dw_w   = (const float*)d_in[7];
    const float* pw_w   = (const float*)d_in[8];
    const float* pw_b   = (const float*)d_in[9];
    const float* dec_w1 = (const float*)d_in[10];
    const float* dec_b1 = (const float*)d_in[11];
    const float* dec_w2 = (const float*)d_in[12];
    const float* dec_b2 = (const float*)d_in[13];
    const float* dec_w3 = (const float*)d_in[14];
    const float* dec_b3 = (const float*)d_in[15];
    float* out = (float*)d_out;

    float *e1p, *e2p, *hsp, *d1p;
    cudaGetSymbolAddress((void**)&e1p, g_e1p);
    cudaGetSymbolAddress((void**)&e2p, g_e2p);
    cudaGetSymbolAddress((void**)&hsp, g_hsp);
    cudaGetSymbolAddress((void**)&d1p, g_d1p);

    // dynamic smem opt-in (idempotent)
    const int enc2_smem = (ENC2_CC * E1S + ENC2_CC * 72)  * 4;
    const int enc3_smem = (ENC3_CC * E2S + ENC3_CC * 288) * 4;
    const int pw_smem   = (PW_CC   * GWS + PW_CC   * 32)  * 4;
    const int d2_smem   = (D2_CC   * D1S + D2_CC   * 128) * 4;
    cudaFuncSetAttribute(k_enc2,     cudaFuncAttributeMaxDynamicSharedMemorySize, enc2_smem);
    cudaFuncSetAttribute(k_enc3,     cudaFuncAttributeMaxDynamicSharedMemorySize, enc3_smem);
    cudaFuncSetAttribute(k_pw_gates, cudaFuncAttributeMaxDynamicSharedMemorySize, pw_smem);
    cudaFuncSetAttribute(k_dec2,     cudaFuncAttributeMaxDynamicSharedMemorySize, d2_smem);

    // zero state + borders (interiors are rewritten every call)
    k_zero_hc<<<(BB * HD * NP2 + 255) / 256, 256>>>();
    k_border<<<BT * 64, 64>>>(e1p, E1S, 44, 44);

    // encoder
    k_enc1<<<dim3(4, 1, BT), 448>>>(x, enc_w1, enc_b1);
    k_border<<<BT * 128, 64>>>(e2p, E2S, 23, 23);
    k_enc2<<<dim3(1, 128 / 8, BT), 448, enc2_smem>>>(enc_w2, enc_b2);
    k_enc3<<<dim3(256 / 32, BT), 448, enc3_smem>>>(enc_w3, enc_b3);

    // h-independent depthwise(feat), all frames
    k_border<<<BT * 256, 64>>>(hsp, E2S, 23, 23);
    k_dw_feat<<<dim3(256, BT), 448>>>(dw_w);

    // ConvLSTM over T=16 steps
    for (int t = 0; t < TT; t++) {
        k_dw_h<<<dim3(256, BB), 448>>>(dw_w);
        k_pw_gates<<<dim3(32, BB), 448, pw_smem>>>(pw_w, pw_b, t);
    }

    // decoder (folded nearest-upsample convs)
    k_border<<<BT * 128, 64>>>(d1p, D1S, 44, 44);
    k_dec1<<<dim3(128 / 8, BT), 448>>>(dec_w1, dec_b1);
    k_dec2<<<dim3(4, 64 / 8, BT), 448, d2_smem>>>(dec_w2, dec_b2);
    k_dec3<<<(OUTN + 255) / 256, 256>>>(dec_w3, dec_b3, out);

    if (out_size >= 3 * OUTN)
        k_copy_hc<<<(BB * HD * NP2 + 255) / 256, 256>>>(out);
}

// round 11
// speedup vs baseline: 1.0031x; 1.0025x over previous
#include <cuda_runtime.h>
#include <cuda_bf16.h>
#include <math.h>

// ---------------------------------------------------------------------------
//   x: (8,16,3,84,84)  B=8 T=16  -> BT=128 frames
//   enc: 3->64 (pool), 64->128 (pool), 128->256    @84/42/21
//   ConvLSTM: depthwise 3x3 g=512, pointwise 512->1024, gates
//   dec: up2 conv 256->128 @42, up2 conv 128->64 @84, 1x1 64->1
//   Halo-padded buffers; smem fills are linear float4 copies.
//   Big kernels use dynamic smem (>48KB) to halve K-chunk count.
// ---------------------------------------------------------------------------

#define BT   128
#define BB   8
#define TT   16
#define HD   256
#define NP2  441
#define NP0  7056
#define OUTN 903168

#define E1S  1936   // 44*44 padded channel (42x42 interior)
#define E2S  544    // 23*23=529 padded to 544 (21x21 interior)
#define GWS  448    // 441 padded to 448
#define D1S  1936   // 44*44 padded channel (42x42 interior)

__device__ float g_e1p [(size_t)BT * 64  * E1S];
__device__ float g_e2p [(size_t)BT * 128 * E2S];
__device__ float g_feat[(size_t)BT * 256 * NP2];
__device__ float g_gdwf[(size_t)BT * 256 * GWS];
__device__ float g_gdwh[(size_t)BB * 256 * GWS];
__device__ float g_hsp [(size_t)BT * 256 * E2S];
__device__ float g_d1p [(size_t)BT * 128 * D1S];
__device__ float g_d2  [(size_t)BT * 64  * NP0];
__device__ float g_h   [BB * HD * NP2];
__device__ float g_c   [BB * HD * NP2];

__device__ __forceinline__ float sigm(float x) { return 1.0f / (1.0f + expf(-x)); }

// zero only the halo border + stride tail of padded channels.
// grid = #channels, block = 64.
__global__ void k_border(float* buf, int S, int W2, int H2)
{
    float* ch = buf + (size_t)blockIdx.x * S;
    const int nside = H2 - 2;
    const int nb = 2 * W2 + 2 * nside + (S - W2 * H2);
    for (int i = threadIdx.x; i < nb; i += 64) {
        int pos;
        if (i < W2)                       pos = i;
        else if (i < 2 * W2)              pos = (H2 - 1) * W2 + (i - W2);
        else if (i < 2 * W2 + nside)      pos = (i - 2 * W2 + 1) * W2;
        else if (i < 2 * W2 + 2 * nside)  pos = (i - 2 * W2 - nside + 1) * W2 + (W2 - 1);
        else                              pos = W2 * H2 + (i - 2 * W2 - 2 * nside);
        ch[pos] = 0.0f;
    }
}

__global__ void k_zero_hc()
{
    int i = blockIdx.x * blockDim.x + threadIdx.x;
    if (i < BB * HD * NP2) { g_h[i] = 0.0f; g_c[i] = 0.0f; }
}

// ---------------------------------------------------------------------------
// enc1: conv3x3 3->64 + bias + relu + maxpool2.  84x84 -> 42x42 into e1p pad.
// ---------------------------------------------------------------------------
__global__ void __launch_bounds__(448) k_enc1(
    const float* __restrict__ x, const float* __restrict__ w,
    const float* __restrict__ bias)
{
    __shared__ float s_in[3 * 44 * 44];
    __shared__ __align__(16) float s_w[3 * 9 * 64];

    const int n   = blockIdx.z;
    const int bx  = blockIdx.x;
    const int py0 = (bx >> 1) * 21;
    const int px0 = (bx & 1) * 21;
    const int oy0 = py0 * 2;
    const int ox0 = px0 * 2;
    const int tid = threadIdx.x;

    const float* xn = x + (size_t)n * 3 * NP0;

    for (int idx = tid; idx < 3 * 44 * 44; idx += 448) {
        int ci = idx / 1936, rem = idx % 1936;
        int r = rem / 44, c = rem % 44;
        int gy = oy0 - 1 + r, gx = ox0 - 1 + c;
        float v = 0.0f;
        if (gy >= 0 && gy < 84 && gx >= 0 && gx < 84)
            v = xn[(size_t)ci * NP0 + gy * 84 + gx];
        s_in[idx] = v;
    }
    for (int idx = tid; idx < 3 * 9 * 64; idx += 448) {
        int ci = idx / (9 * 64); int k = (idx % (9 * 64)) / 64; int co = idx % 64;
        s_w[idx] = w[((size_t)co * 3 + ci) * 9 + k];
    }
    __syncthreads();
    if (tid >= 441) return;

    const int ty = tid / 21, tx = tid % 21;
    const int by = 2 * ty, bxp = 2 * tx;

    for (int cg = 0; cg < 8; cg++) {
        float acc[8][4];
        #pragma unroll
        for (int j = 0; j < 8; j++) { acc[j][0]=acc[j][1]=acc[j][2]=acc[j][3]=0.f; }
        #pragma unroll
        for (int ci = 0; ci < 3; ci++) {
            const float* si = &s_in[ci * 1936];
            #pragma unroll
            for (int k = 0; k < 9; k++) {
                int dy = k / 3, dx = k % 3;
                const float* p0 = si + (by + dy) * 44 + (bxp + dx);
                float v00 = p0[0], v01 = p0[1], v10 = p0[44], v11 = p0[45];
                float4 wA = *(const float4*)&s_w[(ci * 9 + k) * 64 + cg * 8];
                float4 wB = *(const float4*)&s_w[(ci * 9 + k) * 64 + cg * 8 + 4];
                float wv[8] = {wA.x, wA.y, wA.z, wA.w, wB.x, wB.y, wB.z, wB.w};
                #pragma unroll
                for (int j = 0; j < 8; j++) {
                    acc[j][0] += v00 * wv[j];
                    acc[j][1] += v01 * wv[j];
                    acc[j][2] += v10 * wv[j];
                    acc[j][3] += v11 * wv[j];
                }
            }
        }
        #pragma unroll
        for (int j = 0; j < 8; j++) {
            int co = cg * 8 + j;
            float m = fmaxf(fmaxf(acc[j][0], acc[j][1]), fmaxf(acc[j][2], acc[j][3]));
            m = fmaxf(m + bias[co], 0.0f);
            g_e1p[((size_t)n * 64 + co) * E1S + (py0 + ty + 1) * 44 + (px0 + tx + 1)] = m;
        }
    }
}

// ---------------------------------------------------------------------------
// enc2: conv3x3 64->128 + bias + relu + maxpool2 @42 -> 21 into e2p pad.
// CC=8, dynamic smem (64.3KB), 8 chunks.
// ---------------------------------------------------------------------------
#define ENC2_CC 8
__global__ void __launch_bounds__(448) k_enc2(
    const float* __restrict__ w, const float* __restrict__ bias)
{
    extern __shared__ float smem[];
    float* s_in = smem;                       // ENC2_CC * E1S
    float* s_w  = smem + ENC2_CC * E1S;       // ENC2_CC * 72

    const int n   = blockIdx.z;
    const int coB = blockIdx.y * 8;
    const int tid = threadIdx.x;
    const int ty = tid / 21, tx = tid % 21;
    const int by = 2 * ty, bxp = 2 * tx;

    float acc[8][4];
    #pragma unroll
    for (int j = 0; j < 8; j++) { acc[j][0]=acc[j][1]=acc[j][2]=acc[j][3]=0.f; }

    for (int cc = 0; cc < 64; cc += ENC2_CC) {
        const float4* src4 = (const float4*)&g_e1p[((size_t)n * 64 + cc) * E1S];
        float4* dst4 = (float4*)s_in;
        #pragma unroll 1
        for (int idx = tid; idx < ENC2_CC * (E1S / 4); idx += 448) dst4[idx] = src4[idx];
        for (int idx = tid; idx < ENC2_CC * 72; idx += 448) {
            int ci = idx / 72; int k = (idx % 72) / 8; int co = idx % 8;
            s_w[idx] = w[((size_t)(coB + co) * 64 + (cc + ci)) * 9 + k];
        }
        __syncthreads();
        if (tid < 441) {
            #pragma unroll
            for (int ci = 0; ci < ENC2_CC; ci++) {
                const float* si = &s_in[ci * E1S];
                #pragma unroll
                for (int k = 0; k < 9; k++) {
                    int dy = k / 3, dx = k % 3;
                    const float* p0 = si + (by + dy) * 44 + (bxp + dx);
                    float v00 = p0[0], v01 = p0[1], v10 = p0[44], v11 = p0[45];
                    float4 wA = *(const float4*)&s_w[(ci * 9 + k) * 8];
                    float4 wB = *(const float4*)&s_w[(ci * 9 + k) * 8 + 4];
                    float wv[8] = {wA.x, wA.y, wA.z, wA.w, wB.x, wB.y, wB.z, wB.w};
                    #pragma unroll
                    for (int j = 0; j < 8; j++) {
                        acc[j][0] += v00 * wv[j];
                        acc[j][1] += v01 * wv[j];
                        acc[j][2] += v10 * wv[j];
                        acc[j][3] += v11 * wv[j];
                    }
                }
            }
        }
        __syncthreads();
    }

    if (tid >= 441) return;
    #pragma unroll
    for (int j = 0; j < 8; j++) {
        int co = coB + j;
        float m = fmaxf(fmaxf(acc[j][0], acc[j][1]), fmaxf(acc[j][2], acc[j][3]));
        m = fmaxf(m + bias[co], 0.0f);
        g_e2p[((size_t)n * 128 + co) * E2S + (ty + 1) * 23 + (tx + 1)] = m;
    }
}

// ---------------------------------------------------------------------------
// enc3: conv3x3 128->256 + bias + relu @21x21.  CC=16, dynamic smem (53KB),
// 8 chunks. 448 threads, 1 px x 32 couts.
// ---------------------------------------------------------------------------
#define ENC3_CC 16
__global__ void __launch_bounds__(448) k_enc3(
    const float* __restrict__ w, const float* __restrict__ bias)
{
    extern __shared__ float smem[];
    float* s_in = smem;                       // ENC3_CC * E2S
    float* s_w  = smem + ENC3_CC * E2S;       // ENC3_CC * 288

    const int coB = blockIdx.x * 32;
    const int n   = blockIdx.y;
    const int tid = threadIdx.x;
    const int y = tid / 21, x = tid % 21;

    float acc[32];
    #pragma unroll
    for (int j = 0; j < 32; j++) acc[j] = 0.0f;

    for (int cc = 0; cc < 128; cc += ENC3_CC) {
        const float4* src4 = (const float4*)&g_e2p[((size_t)n * 128 + cc) * E2S];
        float4* dst4 = (float4*)s_in;
        #pragma unroll 1
        for (int idx = tid; idx < ENC3_CC * (E2S / 4); idx += 448) dst4[idx] = src4[idx];
        for (int idx = tid; idx < ENC3_CC * 288; idx += 448) {
            int ci = idx / 288; int k = (idx % 288) / 32; int co = idx % 32;
            s_w[idx] = w[((size_t)(coB + co) * 128 + (cc + ci)) * 9 + k];
        }
        __syncthreads();
        if (tid < 441) {
            #pragma unroll
            for (int ci = 0; ci < ENC3_CC; ci++) {
                const float* si = &s_in[ci * E2S + y * 23 + x];
                float v[9];
                #pragma unroll
                for (int r = 0; r < 3; r++) {
                    v[r*3+0] = si[r*23+0]; v[r*3+1] = si[r*23+1]; v[r*3+2] = si[r*23+2];
                }
                #pragma unroll
                for (int k = 0; k < 9; k++) {
                    float vv = v[k];
                    const float* wb = &s_w[(ci * 9 + k) * 32];
                    #pragma unroll
                    for (int q = 0; q < 8; q++) {
                        float4 wq = *(const float4*)(wb + q * 4);
                        acc[q*4+0] += vv * wq.x;
                        acc[q*4+1] += vv * wq.y;
                        acc[q*4+2] += vv * wq.z;
                        acc[q*4+3] += vv * wq.w;
                    }
                }
            }
        }
        __syncthreads();
    }

    if (tid >= 441) return;
    #pragma unroll
    for (int j = 0; j < 32; j++) {
        int co = coB + j;
        g_feat[((size_t)n * 256 + co) * NP2 + tid] = fmaxf(acc[j] + bias[co], 0.0f);
    }
}

// ---------------------------------------------------------------------------
// depthwise conv 3x3 — feat half (ch 0..255), ALL frames
// ---------------------------------------------------------------------------
__global__ void __launch_bounds__(448) k_dw_feat(const float* __restrict__ dww)
{
    __shared__ float s[NP2];
    const int ch  = blockIdx.x;
    const int n   = blockIdx.y;
    const int tid = threadIdx.x;

    const float* src = &g_feat[((size_t)n * 256 + ch) * NP2];
    if (tid < NP2) s[tid] = src[tid];
    __syncthreads();
    if (tid >= NP2) return;

    float wr[9];
    #pragma unroll
    for (int k = 0; k < 9; k++) wr[k] = __ldg(&dww[(size_t)ch * 9 + k]);

    int y = tid / 21, x = tid % 21;
    float acc = 0.0f;
    #pragma unroll
    for (int k = 0; k < 9; k++) {
        int iy = y + k / 3 - 1, ix = x + k % 3 - 1;
        if (iy >= 0 && iy < 21 && ix >= 0 && ix < 21)
            acc += s[iy * 21 + ix] * wr[k];
    }
    g_gdwf[((size_t)n * 256 + ch) * GWS + tid] = acc;
}

// depthwise conv — h half (ch 256..511), per step
__global__ void __launch_bounds__(448) k_dw_h(const float* __restrict__ dww)
{
    __shared__ float s[NP2];
    const int ch  = blockIdx.x;
    const int b   = blockIdx.y;
    const int tid = threadIdx.x;

    const float* src = &g_h[((size_t)b * HD + ch) * NP2];
    if (tid < NP2) s[tid] = src[tid];
    __syncthreads();
    if (tid >= NP2) return;

    float wr[9];
    #pragma unroll
    for (int k = 0; k < 9; k++) wr[k] = __ldg(&dww[(size_t)(256 + ch) * 9 + k]);

    int y = tid / 21, x = tid % 21;
    float acc = 0.0f;
    #pragma unroll
    for (int k = 0; k < 9; k++) {
        int iy = y + k / 3 - 1, ix = x + k % 3 - 1;
        if (iy >= 0 && iy < 21 && ix >= 0 && ix < 21)
            acc += s[iy * 21 + ix] * wr[k];
    }
    g_gdwh[((size_t)b * 256 + ch) * GWS + tid] = acc;
}

// ---------------------------------------------------------------------------
// pointwise 1x1 512->1024 + bias + LSTM gates.  CC=32, dynamic smem (61.4KB),
// 16 chunks.  grid (32, 8).
// ---------------------------------------------------------------------------
#define PW_CC 32
__global__ void __launch_bounds__(448) k_pw_gates(
    const float* __restrict__ pww, const float* __restrict__ pwb, int t)
{
    extern __shared__ float smem[];
    float* s_in = smem;                       // PW_CC * GWS
    float* s_w  = smem + PW_CC * GWS;         // PW_CC * 32

    const int coB = blockIdx.x * 8;
    const int b   = blockIdx.y;
    const int tid = threadIdx.x;

    float acc[32];
    #pragma unroll
    for (int j = 0; j < 32; j++) acc[j] = 0.0f;

    for (int cc = 0; cc < 512; cc += PW_CC) {
        const float* src = (cc < 256)
            ? &g_gdwf[((size_t)(b * TT + t) * 256 + cc) * GWS]
            : &g_gdwh[((size_t)b * 256 + (cc - 256)) * GWS];
        const float4* src4 = (const float4*)src;
        float4* dst4 = (float4*)s_in;
        #pragma unroll 1
        for (int idx = tid; idx < PW_CC * (GWS / 4); idx += 448) dst4[idx] = src4[idx];
        for (int idx = tid; idx < PW_CC * 32; idx += 448) {
            int ci = idx >> 5, j = idx & 31;
            int gate = j >> 3, co = j & 7;
            s_w[idx] = pww[((size_t)(gate * 256 + coB + co)) * 512 + cc + ci];
        }
        __syncthreads();
        if (tid < NP2) {
            #pragma unroll
            for (int ci = 0; ci < PW_CC; ci++) {
                float v = s_in[ci * GWS + tid];
                const float* fw = &s_w[ci * 32];
                #pragma unroll
                for (int q = 0; q < 8; q++) {
                    float4 wq = *(const float4*)(fw + q * 4);
                    acc[q*4+0] += v * wq.x;
                    acc[q*4+1] += v * wq.y;
                    acc[q*4+2] += v * wq.z;
                    acc[q*4+3] += v * wq.w;
                }
            }
        }
        __syncthreads();
    }

    if (tid >= NP2) return;
    const int n = b * TT + t;
    const int y = tid / 21, x = tid % 21;
    const int padpix = (y + 1) * 23 + (x + 1);
    #pragma unroll
    for (int co = 0; co < 8; co++) {
        int cg = coB + co;
        float iv = sigm(acc[co]       + pwb[cg]);
        float fv = sigm(acc[8 + co]   + pwb[256 + cg]);
        float ov = sigm(acc[16 + co]  + pwb[512 + cg]);
        float gv = tanhf(acc[24 + co] + pwb[768 + cg]);
        size_t off = ((size_t)b * HD + cg) * NP2 + tid;
        float c2 = fv * g_c[off] + iv * gv;
        float h2 = ov * tanhf(c2);
        g_c[off] = c2;
        g_h[off] = h2;
        g_hsp[((size_t)n * 256 + cg) * E2S + padpix] = h2;
    }
}

// ---------------------------------------------------------------------------
// dec1: folded up2+conv3x3 256->128 @21->42.  CC=16 static (43KB), 16 chunks.
// ---------------------------------------------------------------------------
#define D1_CC 16
__global__ void __launch_bounds__(448) k_dec1(
    const float* __restrict__ w, const float* __restrict__ bias)
{
    __shared__ __align__(16) float s_in[D1_CC * E2S];
    __shared__ __align__(16) float s_fw[D1_CC * 128];

    const int coB = blockIdx.x * 8;
    const int n   = blockIdx.y;
    const int tid = threadIdx.x;
    const int ty = tid / 21, tx = tid % 21;

    float acc[8][4];
    #pragma unroll
    for (int j = 0; j < 8; j++) { acc[j][0]=acc[j][1]=acc[j][2]=acc[j][3]=0.f; }

    for (int cc = 0; cc < 256; cc += D1_CC) {
        const float4* src4 = (const float4*)&g_hsp[((size_t)n * 256 + cc) * E2S];
        float4* dst4 = (float4*)s_in;
        #pragma unroll 1
        for (int idx = tid; idx < D1_CC * (E2S / 4); idx += 448) dst4[idx] = src4[idx];
        for (int idx = tid; idx < D1_CC * 128; idx += 448) {
            int ci = idx >> 7;
            int pt = (idx >> 3) & 15;
            int co = idx & 7;
            int par = pt >> 2, tap = pt & 3;
            int py = par >> 1, px = par & 1, a = tap >> 1, b = tap & 1;
            const float* wb = &w[((size_t)(coB + co) * 256 + cc + ci) * 9];
            int rlo, rhi, clo, chi;
            if (py == 0) { if (a == 0) { rlo = 0; rhi = 0; } else { rlo = 1; rhi = 2; } }
            else         { if (a == 0) { rlo = 0; rhi = 1; } else { rlo = 2; rhi = 2; } }
            if (px == 0) { if (b == 0) { clo = 0; chi = 0; } else { clo = 1; chi = 2; } }
            else         { if (b == 0) { clo = 0; chi = 1; } else { clo = 2; chi = 2; } }
            float s = 0.0f;
            for (int r = rlo; r <= rhi; r++)
                for (int c = clo; c <= chi; c++)
                    s += wb[r * 3 + c];
            s_fw[idx] = s;
        }
        __syncthreads();
        if (tid < 441) {
            #pragma unroll
            for (int ci = 0; ci < D1_CC; ci++) {
                const float* si = &s_in[ci * E2S + ty * 23 + tx];
                float v[3][3];
                #pragma unroll
                for (int r = 0; r < 3; r++) {
                    v[r][0] = si[r*23+0]; v[r][1] = si[r*23+1]; v[r][2] = si[r*23+2];
                }
                const float* fw = &s_fw[ci * 128];
                #pragma unroll
                for (int par = 0; par < 4; par++) {
                    const int py = par >> 1, px = par & 1;
                    #pragma unroll
                    for (int tap = 0; tap < 4; tap++) {
                        const int a = tap >> 1, b = tap & 1;
                        float vv = v[py + a][px + b];
                        float4 wA = *(const float4*)&fw[(par * 4 + tap) * 8];
                        float4 wB = *(const float4*)&fw[(par * 4 + tap) * 8 + 4];
                        acc[0][par] += vv * wA.x;  acc[1][par] += vv * wA.y;
                        acc[2][par] += vv * wA.z;  acc[3][par] += vv * wA.w;
                        acc[4][par] += vv * wB.x;  acc[5][par] += vv * wB.y;
                        acc[6][par] += vv * wB.z;  acc[7][par] += vv * wB.w;
                    }
                }
            }
        }
        __syncthreads();
    }

    if (tid >= 441) return;
    #pragma unroll
    for (int j = 0; j < 8; j++) {
        int co = coB + j;
        float bv = bias[co];
        #pragma unroll
        for (int py = 0; py < 2; py++) {
            int Y = ty * 2 + py;
            int X = tx * 2;
            float* op = &g_d1p[((size_t)n * 128 + co) * D1S + (Y + 1) * 44 + (X + 1)];
            op[0] = fmaxf(acc[j][py * 2 + 0] + bv, 0.0f);
            op[1] = fmaxf(acc[j][py * 2 + 1] + bv, 0.0f);
        }
    }
}

// ---------------------------------------------------------------------------
// dec2: folded up2+conv3x3 128->64 @42->84.  CC=8, dynamic smem (66KB),
// 16 chunks.  grid (4 tiles, 8 co-groups, BT).
// ---------------------------------------------------------------------------
#define D2_CC 8
__global__ void __launch_bounds__(448) k_dec2(
    const float* __restrict__ w, const float* __restrict__ bias)
{
    extern __shared__ float smem[];
    float* s_in = smem;                       // D2_CC * D1S
    float* s_fw = smem + D2_CC * D1S;         // D2_CC * 128

    const int n   = blockIdx.z;
    const int coB = blockIdx.y * 8;
    const int tY  = blockIdx.x >> 1;
    const int tX  = blockIdx.x & 1;
    const int y0  = tY * 21, x0 = tX * 21;
    const int tid = threadIdx.x;
    const int ty = tid / 21, tx = tid % 21;

    float acc[8][4];
    #pragma unroll
    for (int j = 0; j < 8; j++) { acc[j][0]=acc[j][1]=acc[j][2]=acc[j][3]=0.f; }

    for (int cc = 0; cc < 128; cc += D2_CC) {
        const float4* src4 = (const float4*)&g_d1p[((size_t)n * 128 + cc) * D1S];
        float4* dst4 = (float4*)s_in;
        #pragma unroll 1
        for (int idx = tid; idx < D2_CC * (D1S / 4); idx += 448) dst4[idx] = src4[idx];
        for (int idx = tid; idx < D2_CC * 128; idx += 448) {
            int ci = idx >> 7;
            int pt = (idx >> 3) & 15;
            int co = idx & 7;
            int par = pt >> 2, tap = pt & 3;
            int py = par >> 1, px = par & 1, a = tap >> 1, b = tap & 1;
            const float* wb = &w[((size_t)(coB + co) * 128 + cc + ci) * 9];
            int rlo, rhi, clo, chi;
            if (py == 0) { if (a == 0) { rlo = 0; rhi = 0; } else { rlo = 1; rhi = 2; } }
            else         { if (a == 0) { rlo = 0; rhi = 1; } else { rlo = 2; rhi = 2; } }
            if (px == 0) { if (b == 0) { clo = 0; chi = 0; } else { clo = 1; chi = 2; } }
            else         { if (b == 0) { clo = 0; chi = 1; } else { clo = 2; chi = 2; } }
            float s = 0.0f;
            for (int r = rlo; r <= rhi; r++)
                for (int c = clo; c <= chi; c++)
                    s += wb[r * 3 + c];
            s_fw[idx] = s;
        }
        __syncthreads();
        if (tid < 441) {
            #pragma unroll
            for (int ci = 0; ci < D2_CC; ci++) {
                const float* si = &s_in[ci * D1S + (y0 + ty) * 44 + (x0 + tx)];
                float v[3][3];
                #pragma unroll
                for (int r = 0; r < 3; r++) {
                    v[r][0] = si[r*44+0]; v[r][1] = si[r*44+1]; v[r][2] = si[r*44+2];
                }
                const float* fw = &s_fw[ci * 128];
                #pragma unroll
                for (int par = 0; par < 4; par++) {
                    const int py = par >> 1, px = par & 1;
                    #pragma unroll
                    for (int tap = 0; tap < 4; tap++) {
                        const int a = tap >> 1, b = tap & 1;
                        float vv = v[py + a][px + b];
                        float4 wA = *(const float4*)&fw[(par * 4 + tap) * 8];
                        float4 wB = *(const float4*)&fw[(par * 4 + tap) * 8 + 4];
                        acc[0][par] += vv * wA.x;  acc[1][par] += vv * wA.y;
                        acc[2][par] += vv * wA.z;  acc[3][par] += vv * wA.w;
                        acc[4][par] += vv * wB.x;  acc[5][par] += vv * wB.y;
                        acc[6][par] += vv * wB.z;  acc[7][par] += vv * wB.w;
                    }
                }
            }
        }
        __syncthreads();
    }

    if (tid >= 441) return;
    #pragma unroll
    for (int j = 0; j < 8; j++) {
        int co = coB + j;
        float bv = bias[co];
        #pragma unroll
        for (int py = 0; py < 2; py++) {
            int Y = (y0 + ty) * 2 + py;
            int X = (x0 + tx) * 2;
            float2 o;
            o.x = fmaxf(acc[j][py * 2 + 0] + bv, 0.0f);
            o.y = fmaxf(acc[j][py * 2 + 1] + bv, 0.0f);
            *(float2*)&g_d2[((size_t)n * 64 + co) * NP0 + Y * 84 + X] = o;
        }
    }
}

// ---------------------------------------------------------------------------
// dec3: 1x1 conv 64->1 + bias.
// ---------------------------------------------------------------------------
__global__ void k_dec3(const float* __restrict__ w, const float* __restrict__ bias,
                       float* __restrict__ out)
{
    __shared__ float s_w[64];
    if (threadIdx.x < 64) s_w[threadIdx.x] = w[threadIdx.x];
    __syncthreads();

    int idx = blockIdx.x * blockDim.x + threadIdx.x;
    if (idx >= OUTN) return;
    int n = idx / NP0, pix = idx % NP0;
    const float* d = &g_d2[(size_t)n * 64 * NP0 + pix];
    float acc = bias[0];
    #pragma unroll
    for (int c = 0; c < 64; c++) acc += d[(size_t)c * NP0] * s_w[c];
    out[idx] = acc;
}

__global__ void k_copy_hc(float* __restrict__ out)
{
    int i = blockIdx.x * blockDim.x + threadIdx.x;
    if (i < BB * HD * NP2) {
        out[OUTN + i]     = g_h[i];
        out[2 * OUTN + i] = g_c[i];
    }
}

// ---------------------------------------------------------------------------
extern "C" void kernel_launch(void* const* d_in, const int* in_sizes, int n_in,
                              void* d_out, int out_size)
{
    const float* x      = (const float*)d_in[0];
    const float* enc_w1 = (const float*)d_in[1];
    const float* enc_b1 = (const float*)d_in[2];
    const float* enc_w2 = (const float*)d_in[3];
    const float* enc_b2 = (const float*)d_in[4];
    const float* enc_w3 = (const float*)d_in[5];
    const float* enc_b3 = (const float*)d_in[6];
    const float* dw_w   = (const float*)d_in[7];
    const float* pw_w   = (const float*)d_in[8];
    const float* pw_b   = (const float*)d_in[9];
    const float* dec_w1 = (const float*)d_in[10];
    const float* dec_b1 = (const float*)d_in[11];
    const float* dec_w2 = (const float*)d_in[12];
    const float* dec_b2 = (const float*)d_in[13];
    const float* dec_w3 = (const float*)d_in[14];
    const float* dec_b3 = (const float*)d_in[15];
    float* out = (float*)d_out;

    float *e1p, *e2p, *hsp, *d1p;
    cudaGetSymbolAddress((void**)&e1p, g_e1p);
    cudaGetSymbolAddress((void**)&e2p, g_e2p);
    cudaGetSymbolAddress((void**)&hsp, g_hsp);
    cudaGetSymbolAddress((void**)&d1p, g_d1p);

    // dynamic smem opt-in (idempotent)
    const int enc2_smem = (ENC2_CC * E1S + ENC2_CC * 72)  * 4;
    const int enc3_smem = (ENC3_CC * E2S + ENC3_CC * 288) * 4;
    const int pw_smem   = (PW_CC   * GWS + PW_CC   * 32)  * 4;
    const int d2_smem   = (D2_CC   * D1S + D2_CC   * 128) * 4;
    cudaFuncSetAttribute(k_enc2,     cudaFuncAttributeMaxDynamicSharedMemorySize, enc2_smem);
    cudaFuncSetAttribute(k_enc3,     cudaFuncAttributeMaxDynamicSharedMemorySize, enc3_smem);
    cudaFuncSetAttribute(k_pw_gates, cudaFuncAttributeMaxDynamicSharedMemorySize, pw_smem);
    cudaFuncSetAttribute(k_dec2,     cudaFuncAttributeMaxDynamicSharedMemorySize, d2_smem);

    // zero state + borders (interiors are rewritten every call)
    k_zero_hc<<<(BB * HD * NP2 + 255) / 256, 256>>>();
    k_border<<<BT * 64, 64>>>(e1p, E1S, 44, 44);

    // encoder
    k_enc1<<<dim3(4, 1, BT), 448>>>(x, enc_w1, enc_b1);
    k_border<<<BT * 128, 64>>>(e2p, E2S, 23, 23);
    k_enc2<<<dim3(1, 128 / 8, BT), 448, enc2_smem>>>(enc_w2, enc_b2);
    k_enc3<<<dim3(256 / 32, BT), 448, enc3_smem>>>(enc_w3, enc_b3);

    // h-independent depthwise(feat), all frames
    k_border<<<BT * 256, 64>>>(hsp, E2S, 23, 23);
    k_dw_feat<<<dim3(256, BT), 448>>>(dw_w);

    // ConvLSTM over T=16 steps
    for (int t = 0; t < TT; t++) {
        k_dw_h<<<dim3(256, BB), 448>>>(dw_w);
        k_pw_gates<<<dim3(32, BB), 448, pw_smem>>>(pw_w, pw_b, t);
    }

    // decoder (folded nearest-upsample convs)
    k_border<<<BT * 128, 64>>>(d1p, D1S, 44, 44);
    k_dec1<<<dim3(128 / 8, BT), 448>>>(dec_w1, dec_b1);
    k_dec2<<<dim3(4, 64 / 8, BT), 448, d2_smem>>>(dec_w2, dec_b2);
    k_dec3<<<(OUTN + 255) / 256, 256>>>(dec_w3, dec_b3, out);

    if (out_size >= 3 * OUTN)
        k_copy_hc<<<(BB * HD * NP2 + 255) / 256, 256>>>(out);
}

// round 12
// speedup vs baseline: 1.0361x; 1.0329x over previous
#include <cuda_runtime.h>
#include <cuda_bf16.h>
#include <math.h>

// ---------------------------------------------------------------------------
//   x: (8,16,3,84,84)  B=8 T=16  -> BT=128 frames
//   enc: 3->64 (pool), 64->128 (pool), 128->256    @84/42/21
//   ConvLSTM: depthwise 3x3 g=512, pointwise 512->1024, gates
//   dec: up2 conv 256->128 @42, up2 conv 128->64 @84, 1x1 64->1
//   Halo-padded buffers; smem fills are pure linear float4 copies.
//   Static smem (<48KB) everywhere: >=2 blocks/SM so fills overlap.
// ---------------------------------------------------------------------------

#define BT   128
#define BB   8
#define TT   16
#define HD   256
#define NP2  441
#define NP0  7056
#define OUTN 903168

#define E1S  1936   // 44*44 padded channel (42x42 interior)
#define E2S  544    // 23*23=529 padded to 544 (21x21 interior)
#define GWS  448    // 441 padded to 448
#define D1S  1936   // 44*44 padded channel (42x42 interior)

__device__ float g_e1p [(size_t)BT * 64  * E1S];
__device__ float g_e2p [(size_t)BT * 128 * E2S];
__device__ float g_feat[(size_t)BT * 256 * NP2];
__device__ float g_gdwf[(size_t)BT * 256 * GWS];
__device__ float g_gdwh[(size_t)BB * 256 * GWS];
__device__ float g_hsp [(size_t)BT * 256 * E2S];
__device__ float g_d1p [(size_t)BT * 128 * D1S];
__device__ float g_d2  [(size_t)BT * 64  * NP0];
__device__ float g_h   [BB * HD * NP2];
__device__ float g_c   [BB * HD * NP2];

__device__ __forceinline__ float sigm(float x) { return 1.0f / (1.0f + expf(-x)); }

// zero only the halo border + stride tail of padded channels.
__global__ void k_border(float* buf, int S, int W2, int H2)
{
    float* ch = buf + (size_t)blockIdx.x * S;
    const int nside = H2 - 2;
    const int nb = 2 * W2 + 2 * nside + (S - W2 * H2);
    for (int i = threadIdx.x; i < nb; i += 64) {
        int pos;
        if (i < W2)                       pos = i;
        else if (i < 2 * W2)              pos = (H2 - 1) * W2 + (i - W2);
        else if (i < 2 * W2 + nside)      pos = (i - 2 * W2 + 1) * W2;
        else if (i < 2 * W2 + 2 * nside)  pos = (i - 2 * W2 - nside + 1) * W2 + (W2 - 1);
        else                              pos = W2 * H2 + (i - 2 * W2 - 2 * nside);
        ch[pos] = 0.0f;
    }
}

__global__ void k_zero_hc()
{
    int i = blockIdx.x * blockDim.x + threadIdx.x;
    if (i < BB * HD * NP2) { g_h[i] = 0.0f; g_c[i] = 0.0f; }
}

// ---------------------------------------------------------------------------
// enc1: conv3x3 3->64 + bias + relu + maxpool2.  84x84 -> 42x42 into e1p pad.
// ---------------------------------------------------------------------------
__global__ void __launch_bounds__(448) k_enc1(
    const float* __restrict__ x, const float* __restrict__ w,
    const float* __restrict__ bias)
{
    __shared__ float s_in[3 * 44 * 44];
    __shared__ __align__(16) float s_w[3 * 9 * 64];

    const int n   = blockIdx.z;
    const int bx  = blockIdx.x;
    const int py0 = (bx >> 1) * 21;
    const int px0 = (bx & 1) * 21;
    const int oy0 = py0 * 2;
    const int ox0 = px0 * 2;
    const int tid = threadIdx.x;

    const float* xn = x + (size_t)n * 3 * NP0;

    for (int idx = tid; idx < 3 * 44 * 44; idx += 448) {
        int ci = idx / 1936, rem = idx % 1936;
        int r = rem / 44, c = rem % 44;
        int gy = oy0 - 1 + r, gx = ox0 - 1 + c;
        float v = 0.0f;
        if (gy >= 0 && gy < 84 && gx >= 0 && gx < 84)
            v = xn[(size_t)ci * NP0 + gy * 84 + gx];
        s_in[idx] = v;
    }
    for (int idx = tid; idx < 3 * 9 * 64; idx += 448) {
        int ci = idx / (9 * 64); int k = (idx % (9 * 64)) / 64; int co = idx % 64;
        s_w[idx] = w[((size_t)co * 3 + ci) * 9 + k];
    }
    __syncthreads();
    if (tid >= 441) return;

    const int ty = tid / 21, tx = tid % 21;
    const int by = 2 * ty, bxp = 2 * tx;

    for (int cg = 0; cg < 8; cg++) {
        float acc[8][4];
        #pragma unroll
        for (int j = 0; j < 8; j++) { acc[j][0]=acc[j][1]=acc[j][2]=acc[j][3]=0.f; }
        #pragma unroll
        for (int ci = 0; ci < 3; ci++) {
            const float* si = &s_in[ci * 1936];
            #pragma unroll
            for (int k = 0; k < 9; k++) {
                int dy = k / 3, dx = k % 3;
                const float* p0 = si + (by + dy) * 44 + (bxp + dx);
                float v00 = p0[0], v01 = p0[1], v10 = p0[44], v11 = p0[45];
                float4 wA = *(const float4*)&s_w[(ci * 9 + k) * 64 + cg * 8];
                float4 wB = *(const float4*)&s_w[(ci * 9 + k) * 64 + cg * 8 + 4];
                float wv[8] = {wA.x, wA.y, wA.z, wA.w, wB.x, wB.y, wB.z, wB.w};
                #pragma unroll
                for (int j = 0; j < 8; j++) {
                    acc[j][0] += v00 * wv[j];
                    acc[j][1] += v01 * wv[j];
                    acc[j][2] += v10 * wv[j];
                    acc[j][3] += v11 * wv[j];
                }
            }
        }
        #pragma unroll
        for (int j = 0; j < 8; j++) {
            int co = cg * 8 + j;
            float m = fmaxf(fmaxf(acc[j][0], acc[j][1]), fmaxf(acc[j][2], acc[j][3]));
            m = fmaxf(m + bias[co], 0.0f);
            g_e1p[((size_t)n * 64 + co) * E1S + (py0 + ty + 1) * 44 + (px0 + tx + 1)] = m;
        }
    }
}

// ---------------------------------------------------------------------------
// enc2: conv3x3 64->128 + bias + relu + maxpool2 @42 -> 21 into e2p pad.
// CC=4, static smem. Fill = linear float4 copy.
// ---------------------------------------------------------------------------
__global__ void __launch_bounds__(448) k_enc2(
    const float* __restrict__ w, const float* __restrict__ bias)
{
    const int CC = 4;
    __shared__ __align__(16) float s_in[CC * E1S];
    __shared__ __align__(16) float s_w[CC * 9 * 8];

    const int n   = blockIdx.z;
    const int coB = blockIdx.y * 8;
    const int tid = threadIdx.x;
    const int ty = tid / 21, tx = tid % 21;
    const int by = 2 * ty, bxp = 2 * tx;

    float acc[8][4];
    #pragma unroll
    for (int j = 0; j < 8; j++) { acc[j][0]=acc[j][1]=acc[j][2]=acc[j][3]=0.f; }

    for (int cc = 0; cc < 64; cc += CC) {
        const float4* src4 = (const float4*)&g_e1p[((size_t)n * 64 + cc) * E1S];
        float4* dst4 = (float4*)s_in;
        #pragma unroll 1
        for (int idx = tid; idx < CC * (E1S / 4); idx += 448) dst4[idx] = src4[idx];
        for (int idx = tid; idx < CC * 9 * 8; idx += 448) {
            int ci = idx / 72; int k = (idx % 72) / 8; int co = idx % 8;
            s_w[idx] = w[((size_t)(coB + co) * 64 + (cc + ci)) * 9 + k];
        }
        __syncthreads();
        if (tid < 441) {
            #pragma unroll
            for (int ci = 0; ci < CC; ci++) {
                const float* si = &s_in[ci * E1S];
                #pragma unroll
                for (int k = 0; k < 9; k++) {
                    int dy = k / 3, dx = k % 3;
                    const float* p0 = si + (by + dy) * 44 + (bxp + dx);
                    float v00 = p0[0], v01 = p0[1], v10 = p0[44], v11 = p0[45];
                    float4 wA = *(const float4*)&s_w[(ci * 9 + k) * 8];
                    float4 wB = *(const float4*)&s_w[(ci * 9 + k) * 8 + 4];
                    float wv[8] = {wA.x, wA.y, wA.z, wA.w, wB.x, wB.y, wB.z, wB.w};
                    #pragma unroll
                    for (int j = 0; j < 8; j++) {
                        acc[j][0] += v00 * wv[j];
                        acc[j][1] += v01 * wv[j];
                        acc[j][2] += v10 * wv[j];
                        acc[j][3] += v11 * wv[j];
                    }
                }
            }
        }
        __syncthreads();
    }

    if (tid >= 441) return;
    #pragma unroll
    for (int j = 0; j < 8; j++) {
        int co = coB + j;
        float m = fmaxf(fmaxf(acc[j][0], acc[j][1]), fmaxf(acc[j][2], acc[j][3]));
        m = fmaxf(m + bias[co], 0.0f);
        g_e2p[((size_t)n * 128 + co) * E2S + (ty + 1) * 23 + (tx + 1)] = m;
    }
}

// ---------------------------------------------------------------------------
// enc3: conv3x3 128->256 + bias + relu @21x21.  CC=8, static smem.
// 448 threads, 1 px x 32 couts.
// ---------------------------------------------------------------------------
__global__ void __launch_bounds__(448) k_enc3(
    const float* __restrict__ w, const float* __restrict__ bias)
{
    const int CC = 8;
    __shared__ __align__(16) float s_in[CC * E2S];
    __shared__ __align__(16) float s_w[CC * 9 * 32];

    const int coB = blockIdx.x * 32;
    const int n   = blockIdx.y;
    const int tid = threadIdx.x;
    const int y = tid / 21, x = tid % 21;

    float acc[32];
    #pragma unroll
    for (int j = 0; j < 32; j++) acc[j] = 0.0f;

    for (int cc = 0; cc < 128; cc += CC) {
        const float4* src4 = (const float4*)&g_e2p[((size_t)n * 128 + cc) * E2S];
        float4* dst4 = (float4*)s_in;
        #pragma unroll 1
        for (int idx = tid; idx < CC * (E2S / 4); idx += 448) dst4[idx] = src4[idx];
        for (int idx = tid; idx < CC * 9 * 32; idx += 448) {
            int ci = idx / 288; int k = (idx % 288) / 32; int co = idx % 32;
            s_w[idx] = w[((size_t)(coB + co) * 128 + (cc + ci)) * 9 + k];
        }
        __syncthreads();
        if (tid < 441) {
            #pragma unroll
            for (int ci = 0; ci < CC; ci++) {
                const float* si = &s_in[ci * E2S + y * 23 + x];
                float v[9];
                #pragma unroll
                for (int r = 0; r < 3; r++) {
                    v[r*3+0] = si[r*23+0]; v[r*3+1] = si[r*23+1]; v[r*3+2] = si[r*23+2];
                }
                #pragma unroll
                for (int k = 0; k < 9; k++) {
                    float vv = v[k];
                    const float* wb = &s_w[(ci * 9 + k) * 32];
                    #pragma unroll
                    for (int q = 0; q < 8; q++) {
                        float4 wq = *(const float4*)(wb + q * 4);
                        acc[q*4+0] += vv * wq.x;
                        acc[q*4+1] += vv * wq.y;
                        acc[q*4+2] += vv * wq.z;
                        acc[q*4+3] += vv * wq.w;
                    }
                }
            }
        }
        __syncthreads();
    }

    if (tid >= 441) return;
    #pragma unroll
    for (int j = 0; j < 32; j++) {
        int co = coB + j;
        g_feat[((size_t)n * 256 + co) * NP2 + tid] = fmaxf(acc[j] + bias[co], 0.0f);
    }
}

// ---------------------------------------------------------------------------
// depthwise conv 3x3 — feat half (ch 0..255), ALL frames
// ---------------------------------------------------------------------------
__global__ void __launch_bounds__(448) k_dw_feat(const float* __restrict__ dww)
{
    __shared__ float s[NP2];
    const int ch  = blockIdx.x;
    const int n   = blockIdx.y;
    const int tid = threadIdx.x;

    const float* src = &g_feat[((size_t)n * 256 + ch) * NP2];
    if (tid < NP2) s[tid] = src[tid];
    __syncthreads();
    if (tid >= NP2) return;

    float wr[9];
    #pragma unroll
    for (int k = 0; k < 9; k++) wr[k] = __ldg(&dww[(size_t)ch * 9 + k]);

    int y = tid / 21, x = tid % 21;
    float acc = 0.0f;
    #pragma unroll
    for (int k = 0; k < 9; k++) {
        int iy = y + k / 3 - 1, ix = x + k % 3 - 1;
        if (iy >= 0 && iy < 21 && ix >= 0 && ix < 21)
            acc += s[iy * 21 + ix] * wr[k];
    }
    g_gdwf[((size_t)n * 256 + ch) * GWS + tid] = acc;
}

// depthwise conv — h half (ch 256..511), per step
__global__ void __launch_bounds__(448) k_dw_h(const float* __restrict__ dww)
{
    __shared__ float s[NP2];
    const int ch  = blockIdx.x;
    const int b   = blockIdx.y;
    const int tid = threadIdx.x;

    const float* src = &g_h[((size_t)b * HD + ch) * NP2];
    if (tid < NP2) s[tid] = src[tid];
    __syncthreads();
    if (tid >= NP2) return;

    float wr[9];
    #pragma unroll
    for (int k = 0; k < 9; k++) wr[k] = __ldg(&dww[(size_t)(256 + ch) * 9 + k]);

    int y = tid / 21, x = tid % 21;
    float acc = 0.0f;
    #pragma unroll
    for (int k = 0; k < 9; k++) {
        int iy = y + k / 3 - 1, ix = x + k % 3 - 1;
        if (iy >= 0 && iy < 21 && ix >= 0 && ix < 21)
            acc += s[iy * 21 + ix] * wr[k];
    }
    g_gdwh[((size_t)b * 256 + ch) * GWS + tid] = acc;
}

// ---------------------------------------------------------------------------
// pointwise 1x1 512->1024 + bias + LSTM gates.  CC=16, static smem (30.7KB).
// Fill = pure linear float4 copy. grid (32, 8).
// ---------------------------------------------------------------------------
__global__ void __launch_bounds__(448) k_pw_gates(
    const float* __restrict__ pww, const float* __restrict__ pwb, int t)
{
    const int CC = 16;
    __shared__ __align__(16) float s_in[CC * GWS];
    __shared__ __align__(16) float s_w[CC * 32];

    const int coB = blockIdx.x * 8;
    const int b   = blockIdx.y;
    const int tid = threadIdx.x;

    float acc[32];
    #pragma unroll
    for (int j = 0; j < 32; j++) acc[j] = 0.0f;

    for (int cc = 0; cc < 512; cc += CC) {
        const float* src = (cc < 256)
            ? &g_gdwf[((size_t)(b * TT + t) * 256 + cc) * GWS]
            : &g_gdwh[((size_t)b * 256 + (cc - 256)) * GWS];
        const float4* src4 = (const float4*)src;
        float4* dst4 = (float4*)s_in;
        #pragma unroll 1
        for (int idx = tid; idx < CC * (GWS / 4); idx += 448) dst4[idx] = src4[idx];
        for (int idx = tid; idx < CC * 32; idx += 448) {
            int ci = idx >> 5, j = idx & 31;
            int gate = j >> 3, co = j & 7;
            s_w[idx] = pww[((size_t)(gate * 256 + coB + co)) * 512 + cc + ci];
        }
        __syncthreads();
        if (tid < NP2) {
            #pragma unroll
            for (int ci = 0; ci < CC; ci++) {
                float v = s_in[ci * GWS + tid];
                const float* fw = &s_w[ci * 32];
                #pragma unroll
                for (int q = 0; q < 8; q++) {
                    float4 wq = *(const float4*)(fw + q * 4);
                    acc[q*4+0] += v * wq.x;
                    acc[q*4+1] += v * wq.y;
                    acc[q*4+2] += v * wq.z;
                    acc[q*4+3] += v * wq.w;
                }
            }
        }
        __syncthreads();
    }

    if (tid >= NP2) return;
    const int n = b * TT + t;
    const int y = tid / 21, x = tid % 21;
    const int padpix = (y + 1) * 23 + (x + 1);
    #pragma unroll
    for (int co = 0; co < 8; co++) {
        int cg = coB + co;
        float iv = sigm(acc[co]       + pwb[cg]);
        float fv = sigm(acc[8 + co]   + pwb[256 + cg]);
        float ov = sigm(acc[16 + co]  + pwb[512 + cg]);
        float gv = tanhf(acc[24 + co] + pwb[768 + cg]);
        size_t off = ((size_t)b * HD + cg) * NP2 + tid;
        float c2 = fv * g_c[off] + iv * gv;
        float h2 = ov * tanhf(c2);
        g_c[off] = c2;
        g_h[off] = h2;
        g_hsp[((size_t)n * 256 + cg) * E2S + padpix] = h2;
    }
}

// ---------------------------------------------------------------------------
// dec1: folded up2+conv3x3 256->128 @21->42.  CC=8, static smem.
// ---------------------------------------------------------------------------
__global__ void __launch_bounds__(448) k_dec1(
    const float* __restrict__ w, const float* __restrict__ bias)
{
    const int CC = 8;
    __shared__ __align__(16) float s_in[CC * E2S];
    __shared__ __align__(16) float s_fw[CC * 128];

    const int coB = blockIdx.x * 8;
    const int n   = blockIdx.y;
    const int tid = threadIdx.x;
    const int ty = tid / 21, tx = tid % 21;

    float acc[8][4];
    #pragma unroll
    for (int j = 0; j < 8; j++) { acc[j][0]=acc[j][1]=acc[j][2]=acc[j][3]=0.f; }

    for (int cc = 0; cc < 256; cc += CC) {
        const float4* src4 = (const float4*)&g_hsp[((size_t)n * 256 + cc) * E2S];
        float4* dst4 = (float4*)s_in;
        #pragma unroll 1
        for (int idx = tid; idx < CC * (E2S / 4); idx += 448) dst4[idx] = src4[idx];
        for (int idx = tid; idx < CC * 128; idx += 448) {
            int ci = idx >> 7;
            int pt = (idx >> 3) & 15;
            int co = idx & 7;
            int par = pt >> 2, tap = pt & 3;
            int py = par >> 1, px = par & 1, a = tap >> 1, b = tap & 1;
            const float* wb = &w[((size_t)(coB + co) * 256 + cc + ci) * 9];
            int rlo, rhi, clo, chi;
            if (py == 0) { if (a == 0) { rlo = 0; rhi = 0; } else { rlo = 1; rhi = 2; } }
            else         { if (a == 0) { rlo = 0; rhi = 1; } else { rlo = 2; rhi = 2; } }
            if (px == 0) { if (b == 0) { clo = 0; chi = 0; } else { clo = 1; chi = 2; } }
            else         { if (b == 0) { clo = 0; chi = 1; } else { clo = 2; chi = 2; } }
            float s = 0.0f;
            for (int r = rlo; r <= rhi; r++)
                for (int c = clo; c <= chi; c++)
                    s += wb[r * 3 + c];
            s_fw[idx] = s;
        }
        __syncthreads();
        if (tid < 441) {
            #pragma unroll
            for (int ci = 0; ci < CC; ci++) {
                const float* si = &s_in[ci * E2S + ty * 23 + tx];
                float v[3][3];
                #pragma unroll
                for (int r = 0; r < 3; r++) {
                    v[r][0] = si[r*23+0]; v[r][1] = si[r*23+1]; v[r][2] = si[r*23+2];
                }
                const float* fw = &s_fw[ci * 128];
                #pragma unroll
                for (int par = 0; par < 4; par++) {
                    const int py = par >> 1, px = par & 1;
                    #pragma unroll
                    for (int tap = 0; tap < 4; tap++) {
                        const int a = tap >> 1, b = tap & 1;
                        float vv = v[py + a][px + b];
                        float4 wA = *(const float4*)&fw[(par * 4 + tap) * 8];
                        float4 wB = *(const float4*)&fw[(par * 4 + tap) * 8 + 4];
                        acc[0][par] += vv * wA.x;  acc[1][par] += vv * wA.y;
                        acc[2][par] += vv * wA.z;  acc[3][par] += vv * wA.w;
                        acc[4][par] += vv * wB.x;  acc[5][par] += vv * wB.y;
                        acc[6][par] += vv * wB.z;  acc[7][par] += vv * wB.w;
                    }
                }
            }
        }
        __syncthreads();
    }

    if (tid >= 441) return;
    #pragma unroll
    for (int j = 0; j < 8; j++) {
        int co = coB + j;
        float bv = bias[co];
        #pragma unroll
        for (int py = 0; py < 2; py++) {
            int Y = ty * 2 + py;
            int X = tx * 2;
            float* op = &g_d1p[((size_t)n * 128 + co) * D1S + (Y + 1) * 44 + (X + 1)];
            op[0] = fmaxf(acc[j][py * 2 + 0] + bv, 0.0f);
            op[1] = fmaxf(acc[j][py * 2 + 1] + bv, 0.0f);
        }
    }
}

// ---------------------------------------------------------------------------
// dec2: folded up2+conv3x3 128->64 @42->84.  CC=4, static smem.
// grid (4 tiles, 8 co-groups, BT).
// ---------------------------------------------------------------------------
__global__ void __launch_bounds__(448) k_dec2(
    const float* __restrict__ w, const float* __restrict__ bias)
{
    const int CC = 4;
    __shared__ __align__(16) float s_in[CC * D1S];
    __shared__ __align__(16) float s_fw[CC * 128];

    const int n   = blockIdx.z;
    const int coB = blockIdx.y * 8;
    const int tY  = blockIdx.x >> 1;
    const int tX  = blockIdx.x & 1;
    const int y0  = tY * 21, x0 = tX * 21;
    const int tid = threadIdx.x;
    const int ty = tid / 21, tx = tid % 21;

    float acc[8][4];
    #pragma unroll
    for (int j = 0; j < 8; j++) { acc[j][0]=acc[j][1]=acc[j][2]=acc[j][3]=0.f; }

    for (int cc = 0; cc < 128; cc += CC) {
        const float4* src4 = (const float4*)&g_d1p[((size_t)n * 128 + cc) * D1S];
        float4* dst4 = (float4*)s_in;
        #pragma unroll 1
        for (int idx = tid; idx < CC * (D1S / 4); idx += 448) dst4[idx] = src4[idx];
        for (int idx = tid; idx < CC * 128; idx += 448) {
            int ci = idx >> 7;
            int pt = (idx >> 3) & 15;
            int co = idx & 7;
            int par = pt >> 2, tap = pt & 3;
            int py = par >> 1, px = par & 1, a = tap >> 1, b = tap & 1;
            const float* wb = &w[((size_t)(coB + co) * 128 + cc + ci) * 9];
            int rlo, rhi, clo, chi;
            if (py == 0) { if (a == 0) { rlo = 0; rhi = 0; } else { rlo = 1; rhi = 2; } }
            else         { if (a == 0) { rlo = 0; rhi = 1; } else { rlo = 2; rhi = 2; } }
            if (px == 0) { if (b == 0) { clo = 0; chi = 0; } else { clo = 1; chi = 2; } }
            else         { if (b == 0) { clo = 0; chi = 1; } else { clo = 2; chi = 2; } }
            float s = 0.0f;
            for (int r = rlo; r <= rhi; r++)
                for (int c = clo; c <= chi; c++)
                    s += wb[r * 3 + c];
            s_fw[idx] = s;
        }
        __syncthreads();
        if (tid < 441) {
            #pragma unroll
            for (int ci = 0; ci < CC; ci++) {
                const float* si = &s_in[ci * D1S + (y0 + ty) * 44 + (x0 + tx)];
                float v[3][3];
                #pragma unroll
                for (int r = 0; r < 3; r++) {
                    v[r][0] = si[r*44+0]; v[r][1] = si[r*44+1]; v[r][2] = si[r*44+2];
                }
                const float* fw = &s_fw[ci * 128];
                #pragma unroll
                for (int par = 0; par < 4; par++) {
                    const int py = par >> 1, px = par & 1;
                    #pragma unroll
                    for (int tap = 0; tap < 4; tap++) {
                        const int a = tap >> 1, b = tap & 1;
                        float vv = v[py + a][px + b];
                        float4 wA = *(const float4*)&fw[(par * 4 + tap) * 8];
                        float4 wB = *(const float4*)&fw[(par * 4 + tap) * 8 + 4];
                        acc[0][par] += vv * wA.x;  acc[1][par] += vv * wA.y;
                        acc[2][par] += vv * wA.z;  acc[3][par] += vv * wA.w;
                        acc[4][par] += vv * wB.x;  acc[5][par] += vv * wB.y;
                        acc[6][par] += vv * wB.z;  acc[7][par] += vv * wB.w;
                    }
                }
            }
        }
        __syncthreads();
    }

    if (tid >= 441) return;
    #pragma unroll
    for (int j = 0; j < 8; j++) {
        int co = coB + j;
        float bv = bias[co];
        #pragma unroll
        for (int py = 0; py < 2; py++) {
            int Y = (y0 + ty) * 2 + py;
            int X = (x0 + tx) * 2;
            float2 o;
            o.x = fmaxf(acc[j][py * 2 + 0] + bv, 0.0f);
            o.y = fmaxf(acc[j][py * 2 + 1] + bv, 0.0f);
            *(float2*)&g_d2[((size_t)n * 64 + co) * NP0 + Y * 84 + X] = o;
        }
    }
}

// ---------------------------------------------------------------------------
// dec3: 1x1 conv 64->1 + bias.
// ---------------------------------------------------------------------------
__global__ void k_dec3(const float* __restrict__ w, const float* __restrict__ bias,
                       float* __restrict__ out)
{
    __shared__ float s_w[64];
    if (threadIdx.x < 64) s_w[threadIdx.x] = w[threadIdx.x];
    __syncthreads();

    int idx = blockIdx.x * blockDim.x + threadIdx.x;
    if (idx >= OUTN) return;
    int n = idx / NP0, pix = idx % NP0;
    const float* d = &g_d2[(size_t)n * 64 * NP0 + pix];
    float acc = bias[0];
    #pragma unroll
    for (int c = 0; c < 64; c++) acc += d[(size_t)c * NP0] * s_w[c];
    out[idx] = acc;
}

__global__ void k_copy_hc(float* __restrict__ out)
{
    int i = blockIdx.x * blockDim.x + threadIdx.x;
    if (i < BB * HD * NP2) {
        out[OUTN + i]     = g_h[i];
        out[2 * OUTN + i] = g_c[i];
    }
}

// ---------------------------------------------------------------------------
extern "C" void kernel_launch(void* const* d_in, const int* in_sizes, int n_in,
                              void* d_out, int out_size)
{
    const float* x      = (const float*)d_in[0];
    const float* enc_w1 = (const float*)d_in[1];
    const float* enc_b1 = (const float*)d_in[2];
    const float* enc_w2 = (const float*)d_in[3];
    const float* enc_b2 = (const float*)d_in[4];
    const float* enc_w3 = (const float*)d_in[5];
    const float* enc_b3 = (const float*)d_in[6];
    const float* dw_w   = (const float*)d_in[7];
    const float* pw_w   = (const float*)d_in[8];
    const float* pw_b   = (const float*)d_in[9];
    const float* dec_w1 = (const float*)d_in[10];
    const float* dec_b1 = (const float*)d_in[11];
    const float* dec_w2 = (const float*)d_in[12];
    const float* dec_b2 = (const float*)d_in[13];
    const float* dec_w3 = (const float*)d_in[14];
    const float* dec_b3 = (const float*)d_in[15];
    float* out = (float*)d_out;

    float *e1p, *e2p, *hsp, *d1p;
    cudaGetSymbolAddress((void**)&e1p, g_e1p);
    cudaGetSymbolAddress((void**)&e2p, g_e2p);
    cudaGetSymbolAddress((void**)&hsp, g_hsp);
    cudaGetSymbolAddress((void**)&d1p, g_d1p);

    // zero state + halo borders only (interiors rewritten every call)
    k_zero_hc<<<(BB * HD * NP2 + 255) / 256, 256>>>();
    k_border<<<BT * 64, 64>>>(e1p, E1S, 44, 44);

    // encoder
    k_enc1<<<dim3(4, 1, BT), 448>>>(x, enc_w1, enc_b1);
    k_border<<<BT * 128, 64>>>(e2p, E2S, 23, 23);
    k_enc2<<<dim3(1, 128 / 8, BT), 448>>>(enc_w2, enc_b2);
    k_enc3<<<dim3(256 / 32, BT), 448>>>(enc_w3, enc_b3);

    // h-independent depthwise(feat), all frames
    k_border<<<BT * 256, 64>>>(hsp, E2S, 23, 23);
    k_dw_feat<<<dim3(256, BT), 448>>>(dw_w);

    // ConvLSTM over T=16 steps
    for (int t = 0; t < TT; t++) {
        k_dw_h<<<dim3(256, BB), 448>>>(dw_w);
        k_pw_gates<<<dim3(32, BB), 448>>>(pw_w, pw_b, t);
    }

    // decoder (folded nearest-upsample convs)
    k_border<<<BT * 128, 64>>>(d1p, D1S, 44, 44);
    k_dec1<<<dim3(128 / 8, BT), 448>>>(dec_w1, dec_b1);
    k_dec2<<<dim3(4, 64 / 8, BT), 448>>>(dec_w2, dec_b2);
    k_dec3<<<(OUTN + 255) / 256, 256>>>(dec_w3, dec_b3, out);

    if (out_size >= 3 * OUTN)
        k_copy_hc<<<(BB * HD * NP2 + 255) / 256, 256>>>(out);
}